// round 13
// baseline (speedup 1.0000x reference)
#include <cuda_runtime.h>
#include <cuda_bf16.h>
#include <math.h>
#include <stdint.h>

// ---------------------------------------------------------------------------
// Problem constants
// ---------------------------------------------------------------------------
#define BB     8
#define NN     3136
#define HH_    56
#define WW_    56
#define DM     512
#define NH     4
#define HQ     128
#define HV     256
#define CH     64
#define NCH    49
#define MROWS  (BB*NN)       // 25088

// ---------------------------------------------------------------------------
// Scratch
// ---------------------------------------------------------------------------
static __device__ float g_xs   [MROWS*DM];
static __device__ __nv_bfloat16 g_xs_h[MROWS*DM];
static __device__ __nv_bfloat16 g_xs_l[MROWS*DM];
static __device__ float g_qkv  [MROWS*2048];
static __device__ float g_g    [MROWS*1024];
static __device__ float g_gklat[MROWS*16];
static __device__ float g_gk   [MROWS*1024];
static __device__ float g_of   [MROWS*1024];
static __device__ float g_ob   [MROWS*1024];
static __device__ __nv_bfloat16 g_oc_h[MROWS*1024];
static __device__ __nv_bfloat16 g_oc_l[MROWS*1024];
static __device__ __nv_bfloat16 g_wq_h[2048*512], g_wq_l[2048*512];
static __device__ __nv_bfloat16 g_wg_h[1024*512], g_wg_l[1024*512];
static __device__ __nv_bfloat16 g_wo_h[512*1024], g_wo_l[512*1024];

// ---------------------------------------------------------------------------
// fast exp on the FMA/ALU pipes (no MUFU).
// 2^(x*log2e) via magic-constant round + degree-6 Taylor of 2^f, f in [-.5,.5]
// rel err ~1e-7 over the range used here.
// ---------------------------------------------------------------------------
__device__ __forceinline__ float fast_exp(float x) {
    float t = x * 1.4426950408889634f;
    float z = t + 12582912.0f;            // 1.5 * 2^23
    int   n = __float_as_int(z);          // low bits hold round(t)
    float fr = t - (z - 12582912.0f);     // f in [-0.5, 0.5]
    float p = 0.00015403530393381608f;
    p = fmaf(p, fr, 0.0013333558146428443f);
    p = fmaf(p, fr, 0.009618129107628477f);
    p = fmaf(p, fr, 0.05550410866482158f);
    p = fmaf(p, fr, 0.2402265069591007f);
    p = fmaf(p, fr, 0.6931471805599453f);
    p = fmaf(p, fr, 1.0f);
    return __int_as_float(__float_as_int(p) + (n << 23));
}
__device__ __forceinline__ float sigm(float x) {
    return __fdividef(1.f, 1.f + fast_exp(-x));
}

__device__ __forceinline__ uint32_t smem_u32(const void* p) {
    uint32_t a;
    asm("{ .reg .u64 t; cvta.to.shared.u64 t, %1; cvt.u32.u64 %0, t; }" : "=r"(a) : "l"(p));
    return a;
}
__device__ __forceinline__ void cp16(uint32_t dst, const void* src) {
    asm volatile("cp.async.cg.shared.global [%0], [%1], 16;" :: "r"(dst), "l"(src));
}
#define CP_COMMIT() asm volatile("cp.async.commit_group;" ::: "memory")
#define CP_WAIT0()  asm volatile("cp.async.wait_group 0;" ::: "memory")
#define CP_WAIT1()  asm volatile("cp.async.wait_group 1;" ::: "memory")

__device__ __forceinline__ void ldsm4(uint32_t* r, uint32_t addr) {
    asm volatile("ldmatrix.sync.aligned.m8n8.x4.shared.b16 {%0,%1,%2,%3}, [%4];"
        : "=r"(r[0]), "=r"(r[1]), "=r"(r[2]), "=r"(r[3]) : "r"(addr));
}
__device__ __forceinline__ void ldsm4t(uint32_t* r, uint32_t addr) {
    asm volatile("ldmatrix.sync.aligned.m8n8.x4.trans.shared.b16 {%0,%1,%2,%3}, [%4];"
        : "=r"(r[0]), "=r"(r[1]), "=r"(r[2]), "=r"(r[3]) : "r"(addr));
}
__device__ __forceinline__ void mma16816(float* c, const uint32_t* a, uint32_t b0, uint32_t b1) {
    asm volatile("mma.sync.aligned.m16n8k16.row.col.f32.bf16.bf16.f32 "
        "{%0,%1,%2,%3}, {%4,%5,%6,%7}, {%8,%9}, {%0,%1,%2,%3};"
        : "+f"(c[0]), "+f"(c[1]), "+f"(c[2]), "+f"(c[3])
        : "r"(a[0]), "r"(a[1]), "r"(a[2]), "r"(a[3]), "r"(b0), "r"(b1));
}

__device__ __forceinline__ uint32_t packbf2(float a, float b) {
    __nv_bfloat162 t;
    t.x = __float2bfloat16(a);
    t.y = __float2bfloat16(b);
    return *(uint32_t*)&t;
}

extern __shared__ char s_dyn[];

// ---------------------------------------------------------------------------
// 1) depthwise 3x3 conv + SiLU, emit fp32 + bf16 hi/lo
// ---------------------------------------------------------------------------
__global__ void __launch_bounds__(512) conv_silu_k(const float* __restrict__ x,
                                                   const float* __restrict__ w)
{
    int bn = blockIdx.x;
    int b  = bn / NN, n = bn % NN;
    int y  = n / WW_, xx = n % WW_;
    int c  = threadIdx.x;
    float wr[9];
#pragma unroll
    for (int i = 0; i < 9; ++i) wr[i] = w[c*9 + i];
    float acc = 0.f;
#pragma unroll
    for (int ky = 0; ky < 3; ++ky) {
        int yy = y + ky - 1;
        if (yy < 0 || yy >= HH_) continue;
#pragma unroll
        for (int kx = 0; kx < 3; ++kx) {
            int xc = xx + kx - 1;
            if (xc < 0 || xc >= WW_) continue;
            acc += x[(b*NN + yy*WW_ + xc)*DM + c] * wr[ky*3 + kx];
        }
    }
    float r = acc * sigm(acc);
    g_xs[bn*DM + c] = r;
    __nv_bfloat16 h = __float2bfloat16(r);
    g_xs_h[bn*DM + c] = h;
    g_xs_l[bn*DM + c] = __float2bfloat16(r - __bfloat162float(h));
}

// ---------------------------------------------------------------------------
// hi/lo conversion for weights
// ---------------------------------------------------------------------------
__global__ void __launch_bounds__(256) cvt_hilo_k(const float* __restrict__ s,
                                                  __nv_bfloat16* __restrict__ h,
                                                  __nv_bfloat16* __restrict__ l, int n)
{
    int i = blockIdx.x*256 + threadIdx.x;
    if (i < n) {
        float v = s[i];
        __nv_bfloat16 hh = __float2bfloat16(v);
        h[i] = hh;
        l[i] = __float2bfloat16(v - __bfloat162float(hh));
    }
}

// ---------------------------------------------------------------------------
// 2) bf16x3 GEMM (NT) via mma.sync m16n8k16
// ---------------------------------------------------------------------------
#define GEMM_SMEM (2*4*16384)

template<int EPI>
__global__ void __launch_bounds__(256, 1)
gemm128_k(const __nv_bfloat16* __restrict__ Ah, const __nv_bfloat16* __restrict__ Al,
          const __nv_bfloat16* __restrict__ Bh, const __nv_bfloat16* __restrict__ Bl,
          const float* __restrict__ bias, float* __restrict__ C, int Nc, int K)
{
    const int tid  = threadIdx.x;
    const int lane = tid & 31;
    const int wid  = tid >> 5;
    const int wm   = (wid & 3) * 32;
    const int wn   = (wid >> 2) * 64;
    const int n0 = blockIdx.x * 128, m0 = blockIdx.y * 128;
    const uint32_t sb = smem_u32(s_dyn);
    const int nk = K >> 6;

    float acc[2][8][4];
#pragma unroll
    for (int i = 0; i < 2; ++i)
#pragma unroll
        for (int j = 0; j < 8; ++j)
#pragma unroll
            for (int q = 0; q < 4; ++q) acc[i][j][q] = 0.f;

    auto load_chunk = [&](int kc) {
        uint32_t tb = sb + (kc & 1) * 65536;
        int kb = kc << 6;
#pragma unroll
        for (int it = 0; it < 4; ++it) {
            int i = tid + it*256;
            int row = i >> 3, seg = i & 7;
            uint32_t off = (uint32_t)(row*128 + seg*16);
            uint32_t sw = off ^ ((off >> 3) & 0x70);
            const __nv_bfloat16* pAh = Ah + (size_t)(m0 + row)*K + kb + seg*8;
            const __nv_bfloat16* pAl = Al + (size_t)(m0 + row)*K + kb + seg*8;
            const __nv_bfloat16* pBh = Bh + (size_t)(n0 + row)*K + kb + seg*8;
            const __nv_bfloat16* pBl = Bl + (size_t)(n0 + row)*K + kb + seg*8;
            cp16(tb +         sw, pAh);
            cp16(tb + 16384 + sw, pAl);
            cp16(tb + 32768 + sw, pBh);
            cp16(tb + 49152 + sw, pBl);
        }
    };

    load_chunk(0); CP_COMMIT();

    const int aRow = lane & 15;
    const int aKof = ((lane >> 4) & 1) * 16;
    const int bRowL = (lane & 7) + ((lane & 16) ? 8 : 0);
    const int bKof = (lane & 8) ? 16 : 0;

    for (int c = 0; c < nk; ++c) {
        if (c + 1 < nk) { load_chunk(c + 1); CP_COMMIT(); CP_WAIT1(); }
        else            { CP_WAIT0(); }
        __syncthreads();

        uint32_t tb = sb + (c & 1) * 65536;
#pragma unroll
        for (int ks = 0; ks < 4; ++ks) {
            const int kbyte = ks * 32;
            uint32_t aH[2][4], aL[2][4];
#pragma unroll
            for (int mt = 0; mt < 2; ++mt) {
                uint32_t off = (uint32_t)((wm + mt*16 + aRow) * 128 + kbyte + aKof);
                uint32_t sw = off ^ ((off >> 3) & 0x70);
                ldsm4(aH[mt], tb + sw);
                ldsm4(aL[mt], tb + 16384 + sw);
            }
#pragma unroll
            for (int ntp = 0; ntp < 4; ++ntp) {
                uint32_t off = (uint32_t)((wn + ntp*16 + bRowL) * 128 + kbyte + bKof);
                uint32_t sw = off ^ ((off >> 3) & 0x70);
                uint32_t bh[4], bl[4];
                ldsm4(bh, tb + 32768 + sw);
                ldsm4(bl, tb + 49152 + sw);
#pragma unroll
                for (int mt = 0; mt < 2; ++mt) {
                    mma16816(acc[mt][ntp*2+0], aH[mt], bh[0], bh[1]);
                    mma16816(acc[mt][ntp*2+1], aH[mt], bh[2], bh[3]);
                    mma16816(acc[mt][ntp*2+0], aH[mt], bl[0], bl[1]);
                    mma16816(acc[mt][ntp*2+1], aH[mt], bl[2], bl[3]);
                    mma16816(acc[mt][ntp*2+0], aL[mt], bh[0], bh[1]);
                    mma16816(acc[mt][ntp*2+1], aL[mt], bh[2], bh[3]);
                }
            }
        }
        __syncthreads();
    }

    const int rbase = m0 + wm + (lane >> 2);
    const int cbase = n0 + wn + (lane & 3) * 2;
#pragma unroll
    for (int mt = 0; mt < 2; ++mt) {
#pragma unroll
        for (int nt = 0; nt < 8; ++nt) {
            int col = cbase + nt*8;
#pragma unroll
            for (int half = 0; half < 2; ++half) {
                int row = rbase + mt*16 + half*8;
                float v0 = acc[mt][nt][half*2+0];
                float v1 = acc[mt][nt][half*2+1];
                if (EPI == 1) {
                    v0 += bias[col+0]; v0 *= sigm(v0);
                    v1 += bias[col+1]; v1 *= sigm(v1);
                }
                float2 vv; vv.x = v0; vv.y = v1;
                *(float2*)&C[(size_t)row*Nc + col] = vv;
            }
        }
    }
}

// ---------------------------------------------------------------------------
// 3) gk low-rank stage 1
// ---------------------------------------------------------------------------
__global__ void __launch_bounds__(256) gk1_k(const float* __restrict__ w1)
{
    __shared__ float w1s[16*DM];
    int tid = threadIdx.x;
    for (int i = tid; i < 16*DM; i += 256) w1s[i] = w1[i];
    __syncthreads();
    int m0 = blockIdx.x * 64;
    int j  = tid & 15, rg = tid >> 4;
    const float* xb = &g_xs[(m0 + rg*4)*DM];
    const float4* w4 = (const float4*)&w1s[j*DM];
    float a0 = 0.f, a1 = 0.f, a2 = 0.f, a3 = 0.f;
#pragma unroll 4
    for (int k = 0; k < DM/4; ++k) {
        float4 wv = w4[k];
        float4 x0 = *(const float4*)&xb[0*DM + k*4];
        float4 x1 = *(const float4*)&xb[1*DM + k*4];
        float4 x2 = *(const float4*)&xb[2*DM + k*4];
        float4 x3 = *(const float4*)&xb[3*DM + k*4];
        a0 += x0.x*wv.x + x0.y*wv.y + x0.z*wv.z + x0.w*wv.w;
        a1 += x1.x*wv.x + x1.y*wv.y + x1.z*wv.z + x1.w*wv.w;
        a2 += x2.x*wv.x + x2.y*wv.y + x2.z*wv.z + x2.w*wv.w;
        a3 += x3.x*wv.x + x3.y*wv.y + x3.z*wv.z + x3.w*wv.w;
    }
    g_gklat[(m0+rg*4+0)*16 + j] = a0;
    g_gklat[(m0+rg*4+1)*16 + j] = a1;
    g_gklat[(m0+rg*4+2)*16 + j] = a2;
    g_gklat[(m0+rg*4+3)*16 + j] = a3;
}

// ---------------------------------------------------------------------------
// 4) gk stage 2
// ---------------------------------------------------------------------------
__global__ void __launch_bounds__(256) gk2_k(const float* __restrict__ w2,
                                             const float* __restrict__ b2)
{
    __shared__ float lat[64*16];
    int m0 = blockIdx.y * 64;
    int j  = blockIdx.x * 256 + threadIdx.x;
    for (int i = threadIdx.x; i < 64*16; i += 256) lat[i] = g_gklat[m0*16 + i];
    __syncthreads();
    float w[16];
#pragma unroll
    for (int i = 0; i < 16; ++i) w[i] = w2[j*16 + i];
    float bb = b2[j];
    for (int r = 0; r < 64; ++r) {
        float xv = bb;
#pragma unroll
        for (int i = 0; i < 16; ++i) xv += lat[r*16 + i]*w[i];
        float ls = fminf(xv, 0.f) - log1pf(fast_exp(-fabsf(xv)));
        g_gk[(m0+r)*1024 + j] = ls * (1.f/16.f);
    }
}

// ---------------------------------------------------------------------------
// 5) Chunked GLA — tensorized (mma.sync bf16x3; state fp32 in smem)
//    grid (vs 4, bh 32, dir 2), 256 threads = 8 warps (4m x 2n)
// ---------------------------------------------------------------------------
#define OF_SG    0
#define OF_EBT   33792
#define OF_SF    34304
#define OF_QEH   69120
#define OF_QEL   86528
#define OF_KDH   103936
#define OF_KDL   121344
#define OF_VH    138752
#define OF_VL    147968
#define OF_AH    157184
#define OF_AL    166400
#define OF_SBH   175616
#define OF_SBL   194048
#define GLA_SMEM_BYTES 212480

__global__ void __launch_bounds__(256, 1) gla_k()
{
    char* sm = s_dyn;
    const uint32_t sb = smem_u32(sm);
    float* sg  = (float*)(sm + OF_SG);
    float* ebt = (float*)(sm + OF_EBT);
    float* Sf  = (float*)(sm + OF_SF);

    const int vs  = blockIdx.x;
    const int bh  = blockIdx.y;
    const int dir = blockIdx.z;
    const int b   = bh >> 2;
    const int h   = bh & 3;
    const int tid = threadIdx.x;
    const int lane = tid & 31;
    const int w    = tid >> 5;
    const float scale = 0.088388347648318447f;  // 128^-0.5

    for (int i = tid; i < 128*68; i += 256) Sf[i] = 0.f;
    __syncthreads();

    const int qoff = h*HQ;
    const int koff = 512 + h*HQ;
    const int voff = 1024 + h*HV + vs*64;
    const int goff = dir*512 + h*HQ;
    const int rowb = b*NN;
    float* const outp = dir ? g_ob : g_of;

    const int m0w = (w & 3) * 16;
    const int n0w = (w >> 2) * 32;
    const int m0u = (w & 3) * 32;
    const int aRow = lane & 15;
    const int aSel = ((lane >> 4) & 1) * 16;
    const int bRowL = (lane & 7) + ((lane & 16) ? 8 : 0);
    const int bKof  = (lane & 8) ? 16 : 0;
    const int vRow = (lane & 7) + ((lane >> 3) & 1) * 8;
    const int vSel = ((lane >> 4) & 1) * 16;
    const int tRowT = (lane & 7) + ((lane >> 4) & 1) * 8;
    const int tSelT = ((lane >> 3) & 1) * 16;
    const int g8 = lane >> 2;
    const int q2 = (lane & 3) * 2;

    for (int c = 0; c < NCH; ++c) {
        // ---- P0: load gk chunk -> sg (f32); load+convert v -> v_h/v_l ----
#pragma unroll
        for (int it = 0; it < 8; ++it) {
            int j = tid + it*256;
            int t = j >> 5, d4 = (j & 31) * 4;
            int tg = dir ? (NN-1 - (c*64 + t)) : (c*64 + t);
            *(float4*)&sg[t*132 + d4] = *(const float4*)&g_gk[(size_t)(rowb+tg)*1024 + goff + d4];
        }
#pragma unroll
        for (int it = 0; it < 4; ++it) {
            int j = tid + it*256;
            int s = j >> 4, c4 = (j & 15) * 4;
            int tg = dir ? (NN-1 - (c*64 + s)) : (c*64 + s);
            float4 vv = *(const float4*)&g_qkv[(size_t)(rowb+tg)*2048 + voff + c4];
            __nv_bfloat16 h0 = __float2bfloat16(vv.x), h1 = __float2bfloat16(vv.y);
            __nv_bfloat16 h2 = __float2bfloat16(vv.z), h3 = __float2bfloat16(vv.w);
            uint2 hw, lw;
            hw.x = packbf2(vv.x, vv.y); hw.y = packbf2(vv.z, vv.w);
            lw.x = packbf2(vv.x - __bfloat162float(h0), vv.y - __bfloat162float(h1));
            lw.y = packbf2(vv.z - __bfloat162float(h2), vv.w - __bfloat162float(h3));
            *(uint2*)(sm + OF_VH + s*144 + c4*2) = hw;
            *(uint2*)(sm + OF_VL + s*144 + c4*2) = lw;
        }
        __syncthreads();

        // ---- P1: cumsum along t ----
        if (tid < 128) {
            int d = tid;
            float run = 0.f;
#pragma unroll
            for (int blk = 0; blk < 4; ++blk) {
                float r[16];
#pragma unroll
                for (int i = 0; i < 16; ++i) r[i] = sg[(blk*16+i)*132 + d];
#pragma unroll
                for (int i = 0; i < 16; ++i) { run += r[i]; r[i] = run; }
#pragma unroll
                for (int i = 0; i < 16; ++i) sg[(blk*16+i)*132 + d] = r[i];
            }
            ebt[d] = fast_exp(run);
        }
        __syncthreads();

        // ---- P2: qe/kd conversion + S -> bf16 split ----
#pragma unroll
        for (int it = 0; it < 8; ++it) {
            int j = tid + it*256;
            int t = j >> 5, d4 = (j & 31) * 4;
            int tg = dir ? (NN-1 - (c*64 + t)) : (c*64 + t);
            size_t r = (size_t)(rowb+tg)*2048;
            float4 qv = *(const float4*)&g_qkv[r + qoff + d4];
            float4 kv = *(const float4*)&g_qkv[r + koff + d4];
            float4 bv = *(float4*)&sg[t*132 + d4];
            float e0 = fast_exp(bv.x), e1 = fast_exp(bv.y), e2 = fast_exp(bv.z), e3 = fast_exp(bv.w);
            float f0 = fast_exp(-bv.x), f1 = fast_exp(-bv.y), f2 = fast_exp(-bv.z), f3 = fast_exp(-bv.w);
            float q0 = qv.x*e0*scale, q1 = qv.y*e1*scale, q2v = qv.z*e2*scale, q3 = qv.w*e3*scale;
            float k0 = kv.x*f0, k1 = kv.y*f1, k2 = kv.z*f2, k3 = kv.w*f3;
            __nv_bfloat16 qh0 = __float2bfloat16(q0), qh1 = __float2bfloat16(q1);
            __nv_bfloat16 qh2 = __float2bfloat16(q2v), qh3 = __float2bfloat16(q3);
            __nv_bfloat16 kh0 = __float2bfloat16(k0), kh1 = __float2bfloat16(k1);
            __nv_bfloat16 kh2 = __float2bfloat16(k2), kh3 = __float2bfloat16(k3);
            uint2 qhw, qlw, khw, klw;
            qhw.x = packbf2(q0, q1); qhw.y = packbf2(q2v, q3);
            qlw.x = packbf2(q0 - __bfloat162float(qh0), q1 - __bfloat162float(qh1));
            qlw.y = packbf2(q2v - __bfloat162float(qh2), q3 - __bfloat162float(qh3));
            khw.x = packbf2(k0, k1); khw.y = packbf2(k2, k3);
            klw.x = packbf2(k0 - __bfloat162float(kh0), k1 - __bfloat162float(kh1));
            klw.y = packbf2(k2 - __bfloat162float(kh2), k3 - __bfloat162float(kh3));
            *(uint2*)(sm + OF_QEH + t*272 + d4*2) = qhw;
            *(uint2*)(sm + OF_QEL + t*272 + d4*2) = qlw;
            *(uint2*)(sm + OF_KDH + t*272 + d4*2) = khw;
            *(uint2*)(sm + OF_KDL + t*272 + d4*2) = klw;
        }
#pragma unroll
        for (int it = 0; it < 16; ++it) {
            int j = tid + it*256;
            int d = j >> 5, c2 = (j & 31) * 2;
            float2 sv = *(float2*)&Sf[d*68 + c2];
            __nv_bfloat16 s0 = __float2bfloat16(sv.x), s1 = __float2bfloat16(sv.y);
            *(uint32_t*)(sm + OF_SBH + d*144 + c2*2) = packbf2(sv.x, sv.y);
            *(uint32_t*)(sm + OF_SBL + d*144 + c2*2) =
                packbf2(sv.x - __bfloat162float(s0), sv.y - __bfloat162float(s1));
        }
        __syncthreads();

        // ---- P3: A = qe @ kd^T (64x64, k=128), mask, store bf16 hi/lo ----
        {
            float acc[4][4];
#pragma unroll
            for (int f = 0; f < 4; ++f)
#pragma unroll
                for (int j = 0; j < 4; ++j) acc[f][j] = 0.f;
#pragma unroll
            for (int ks = 0; ks < 8; ++ks) {
                int kb = ks * 32;
                uint32_t aH[4], aL[4];
                ldsm4(aH, sb + OF_QEH + (m0w + aRow)*272 + kb + aSel);
                ldsm4(aL, sb + OF_QEL + (m0w + aRow)*272 + kb + aSel);
                uint32_t bh0[4], bh1[4], bl0[4], bl1[4];
                ldsm4(bh0, sb + OF_KDH + (n0w + bRowL)*272 + kb + bKof);
                ldsm4(bh1, sb + OF_KDH + (n0w + 16 + bRowL)*272 + kb + bKof);
                ldsm4(bl0, sb + OF_KDL + (n0w + bRowL)*272 + kb + bKof);
                ldsm4(bl1, sb + OF_KDL + (n0w + 16 + bRowL)*272 + kb + bKof);
                mma16816(acc[0], aH, bh0[0], bh0[1]);
                mma16816(acc[1], aH, bh0[2], bh0[3]);
                mma16816(acc[2], aH, bh1[0], bh1[1]);
                mma16816(acc[3], aH, bh1[2], bh1[3]);
                mma16816(acc[0], aH, bl0[0], bl0[1]);
                mma16816(acc[1], aH, bl0[2], bl0[3]);
                mma16816(acc[2], aH, bl1[0], bl1[1]);
                mma16816(acc[3], aH, bl1[2], bl1[3]);
                mma16816(acc[0], aL, bh0[0], bh0[1]);
                mma16816(acc[1], aL, bh0[2], bh0[3]);
                mma16816(acc[2], aL, bh1[0], bh1[1]);
                mma16816(acc[3], aL, bh1[2], bh1[3]);
            }
#pragma unroll
            for (int f = 0; f < 4; ++f) {
                int scol = n0w + f*8 + q2;
#pragma unroll
                for (int hh = 0; hh < 2; ++hh) {
                    int t = m0w + g8 + hh*8;
                    float v0 = (scol     <= t) ? acc[f][hh*2+0] : 0.f;
                    float v1 = (scol + 1 <= t) ? acc[f][hh*2+1] : 0.f;
                    __nv_bfloat16 a0 = __float2bfloat16(v0), a1 = __float2bfloat16(v1);
                    *(uint32_t*)(sm + OF_AH + t*144 + scol*2) = packbf2(v0, v1);
                    *(uint32_t*)(sm + OF_AL + t*144 + scol*2) =
                        packbf2(v0 - __bfloat162float(a0), v1 - __bfloat162float(a1));
                }
            }
        }
        __syncthreads();

        // ---- P4: o = A@v + qe@S -> gmem ; U = kd^T @ v ; S update ----
        {
            float acc[4][4];
#pragma unroll
            for (int f = 0; f < 4; ++f)
#pragma unroll
                for (int j = 0; j < 4; ++j) acc[f][j] = 0.f;
            // A @ v  (k = s = 64)
#pragma unroll
            for (int ks = 0; ks < 4; ++ks) {
                int kb = ks * 32;
                uint32_t aH[4], aL[4];
                ldsm4(aH, sb + OF_AH + (m0w + aRow)*144 + kb + aSel);
                ldsm4(aL, sb + OF_AL + (m0w + aRow)*144 + kb + aSel);
                uint32_t b0h[4], b1h[4], b0l[4], b1l[4];
                uint32_t vr = (ks*16 + vRow)*144;
                ldsm4t(b0h, sb + OF_VH + vr + n0w*2 + vSel);
                ldsm4t(b1h, sb + OF_VH + vr + (n0w + 16)*2 + vSel);
                ldsm4t(b0l, sb + OF_VL + vr + n0w*2 + vSel);
                ldsm4t(b1l, sb + OF_VL + vr + (n0w + 16)*2 + vSel);
                mma16816(acc[0], aH, b0h[0], b0h[1]);
                mma16816(acc[1], aH, b0h[2], b0h[3]);
                mma16816(acc[2], aH, b1h[0], b1h[1]);
                mma16816(acc[3], aH, b1h[2], b1h[3]);
                mma16816(acc[0], aH, b0l[0], b0l[1]);
                mma16816(acc[1], aH, b0l[2], b0l[3]);
                mma16816(acc[2], aH, b1l[0], b1l[1]);
                mma16816(acc[3], aH, b1l[2], b1l[3]);
                mma16816(acc[0], aL, b0h[0], b0h[1]);
                mma16816(acc[1], aL, b0h[2], b0h[3]);
                mma16816(acc[2], aL, b1h[0], b1h[1]);
                mma16816(acc[3], aL, b1h[2], b1h[3]);
            }
            // qe @ S  (k = d = 128)
#pragma unroll
            for (int ks = 0; ks < 8; ++ks) {
                int kb = ks * 32;
                uint32_t aH[4], aL[4];
                ldsm4(aH, sb + OF_QEH + (m0w + aRow)*272 + kb + aSel);
                ldsm4(aL, sb + OF_QEL + (m0w + aRow)*272 + kb + aSel);
                uint32_t b0h[4], b1h[4], b0l[4], b1l[4];
                uint32_t sr = (ks*16 + vRow)*144;
                ldsm4t(b0h, sb + OF_SBH + sr + n0w*2 + vSel);
                ldsm4t(b1h, sb + OF_SBH + sr + (n0w + 16)*2 + vSel);
                ldsm4t(b0l, sb + OF_SBL + sr + n0w*2 + vSel);
                ldsm4t(b1l, sb + OF_SBL + sr + (n0w + 16)*2 + vSel);
                mma16816(acc[0], aH, b0h[0], b0h[1]);
                mma16816(acc[1], aH, b0h[2], b0h[3]);
                mma16816(acc[2], aH, b1h[0], b1h[1]);
                mma16816(acc[3], aH, b1h[2], b1h[3]);
                mma16816(acc[0], aH, b0l[0], b0l[1]);
                mma16816(acc[1], aH, b0l[2], b0l[3]);
                mma16816(acc[2], aH, b1l[0], b1l[1]);
                mma16816(acc[3], aH, b1l[2], b1l[3]);
                mma16816(acc[0], aL, b0h[0], b0h[1]);
                mma16816(acc[1], aL, b0h[2], b0h[3]);
                mma16816(acc[2], aL, b1h[0], b1h[1]);
                mma16816(acc[3], aL, b1h[2], b1h[3]);
            }
            // write o
#pragma unroll
            for (int f = 0; f < 4; ++f) {
                int col = n0w + f*8 + q2;
#pragma unroll
                for (int hh = 0; hh < 2; ++hh) {
                    int t = m0w + g8 + hh*8;
                    int tg = dir ? (NN-1 - (c*64 + t)) : (c*64 + t);
                    float2 vv; vv.x = acc[f][hh*2+0]; vv.y = acc[f][hh*2+1];
                    *(float2*)&outp[(size_t)(bh*NN + tg)*256 + vs*64 + col] = vv;
                }
            }
            // U = kd^T @ v  (128x64, k=t=64)
            float au[2][4][4];
#pragma unroll
            for (int mt = 0; mt < 2; ++mt)
#pragma unroll
                for (int f = 0; f < 4; ++f)
#pragma unroll
                    for (int j = 0; j < 4; ++j) au[mt][f][j] = 0.f;
#pragma unroll
            for (int ks = 0; ks < 4; ++ks) {
                uint32_t aTh[2][4], aTl[2][4];
                uint32_t tr = (ks*16 + tRowT)*272;
#pragma unroll
                for (int mt = 0; mt < 2; ++mt) {
                    uint32_t dby = (m0u + mt*16)*2 + tSelT;
                    ldsm4t(aTh[mt], sb + OF_KDH + tr + dby);
                    ldsm4t(aTl[mt], sb + OF_KDL + tr + dby);
                }
                uint32_t b0h[4], b1h[4], b0l[4], b1l[4];
                uint32_t vr = (ks*16 + vRow)*144;
                ldsm4t(b0h, sb + OF_VH + vr + n0w*2 + vSel);
                ldsm4t(b1h, sb + OF_VH + vr + (n0w + 16)*2 + vSel);
                ldsm4t(b0l, sb + OF_VL + vr + n0w*2 + vSel);
                ldsm4t(b1l, sb + OF_VL + vr + (n0w + 16)*2 + vSel);
#pragma unroll
                for (int mt = 0; mt < 2; ++mt) {
                    mma16816(au[mt][0], aTh[mt], b0h[0], b0h[1]);
                    mma16816(au[mt][1], aTh[mt], b0h[2], b0h[3]);
                    mma16816(au[mt][2], aTh[mt], b1h[0], b1h[1]);
                    mma16816(au[mt][3], aTh[mt], b1h[2], b1h[3]);
                    mma16816(au[mt][0], aTh[mt], b0l[0], b0l[1]);
                    mma16816(au[mt][1], aTh[mt], b0l[2], b0l[3]);
                    mma16816(au[mt][2], aTh[mt], b1l[0], b1l[1]);
                    mma16816(au[mt][3], aTh[mt], b1l[2], b1l[3]);
                    mma16816(au[mt][0], aTl[mt], b0h[0], b0h[1]);
                    mma16816(au[mt][1], aTl[mt], b0h[2], b0h[3]);
                    mma16816(au[mt][2], aTl[mt], b1h[0], b1h[1]);
                    mma16816(au[mt][3], aTl[mt], b1h[2], b1h[3]);
                }
            }
            // S = exp(btot) * (S + U)
#pragma unroll
            for (int mt = 0; mt < 2; ++mt) {
#pragma unroll
                for (int f = 0; f < 4; ++f) {
                    int vc = n0w + f*8 + q2;
#pragma unroll
                    for (int hh = 0; hh < 2; ++hh) {
                        int d = m0u + mt*16 + g8 + hh*8;
                        float e = ebt[d];
                        float2 s = *(float2*)&Sf[d*68 + vc];
                        s.x = e * (s.x + au[mt][f][hh*2+0]);
                        s.y = e * (s.y + au[mt][f][hh*2+1]);
                        *(float2*)&Sf[d*68 + vc] = s;
                    }
                }
            }
        }
        __syncthreads();
    }
}

// ---------------------------------------------------------------------------
// 6) combine
// ---------------------------------------------------------------------------
__global__ void __launch_bounds__(256) combine_k(const float* __restrict__ gnw,
                                                 const float* __restrict__ lnw)
{
    __shared__ float red[16];
    int idx = blockIdx.x;
    int bh  = idx / NN, t = idx % NN;
    int b   = bh >> 2,  h = bh & 3;
    int v   = threadIdx.x;
    float of = g_of[(size_t)idx*256 + v];
    float ob = g_ob[(size_t)idx*256 + v];
    float sf = of*of, sb = ob*ob;
#pragma unroll
    for (int o = 16; o > 0; o >>= 1) {
        sf += __shfl_xor_sync(0xffffffffu, sf, o);
        sb += __shfl_xor_sync(0xffffffffu, sb, o);
    }
    int w = v >> 5, l = v & 31;
    if (l == 0) { red[w] = sf; red[8+w] = sb; }
    __syncthreads();
    float tf = 0.f, tb = 0.f;
#pragma unroll
    for (int i = 0; i < 8; ++i) { tf += red[i]; tb += red[8+i]; }
    float inf_ = rsqrtf(tf*(1.f/256.f) + 1e-5f);
    float inb_ = rsqrtf(tb*(1.f/256.f) + 1e-5f);
    float o = of*inf_*gnw[v] + ob*inb_*lnw[v];
    int gi = (b*NN + t)*1024 + h*256 + v;
    float val = o * g_g[gi];
    __nv_bfloat16 hh = __float2bfloat16(val);
    g_oc_h[gi] = hh;
    g_oc_l[gi] = __float2bfloat16(val - __bfloat162float(hh));
}

// ---------------------------------------------------------------------------
// launcher
// ---------------------------------------------------------------------------
extern "C" void kernel_launch(void* const* d_in, const int* in_sizes, int n_in,
                              void* d_out, int out_size)
{
    const float* x     = (const float*)d_in[0];
    const float* convw = (const float*)d_in[1];
    const float* qkvw  = (const float*)d_in[2];
    const float* gkw1  = (const float*)d_in[3];
    const float* gkw2  = (const float*)d_in[4];
    const float* gkb2  = (const float*)d_in[5];
    const float* gw    = (const float*)d_in[6];
    const float* gb    = (const float*)d_in[7];
    const float* gnw   = (const float*)d_in[8];
    const float* lnw   = (const float*)d_in[9];
    const float* ow    = (const float*)d_in[10];
    float* out = (float*)d_out;

    cudaFuncSetAttribute(gla_k, cudaFuncAttributeMaxDynamicSharedMemorySize, GLA_SMEM_BYTES);
    cudaFuncSetAttribute(gemm128_k<0>, cudaFuncAttributeMaxDynamicSharedMemorySize, GEMM_SMEM);
    cudaFuncSetAttribute(gemm128_k<1>, cudaFuncAttributeMaxDynamicSharedMemorySize, GEMM_SMEM);

    float *p_qkv, *p_g;
    __nv_bfloat16 *p_xs_h, *p_xs_l, *p_oc_h, *p_oc_l;
    __nv_bfloat16 *p_wq_h, *p_wq_l, *p_wg_h, *p_wg_l, *p_wo_h, *p_wo_l;
    cudaGetSymbolAddress((void**)&p_qkv,  g_qkv);
    cudaGetSymbolAddress((void**)&p_g,    g_g);
    cudaGetSymbolAddress((void**)&p_xs_h, g_xs_h);
    cudaGetSymbolAddress((void**)&p_xs_l, g_xs_l);
    cudaGetSymbolAddress((void**)&p_oc_h, g_oc_h);
    cudaGetSymbolAddress((void**)&p_oc_l, g_oc_l);
    cudaGetSymbolAddress((void**)&p_wq_h, g_wq_h);
    cudaGetSymbolAddress((void**)&p_wq_l, g_wq_l);
    cudaGetSymbolAddress((void**)&p_wg_h, g_wg_h);
    cudaGetSymbolAddress((void**)&p_wg_l, g_wg_l);
    cudaGetSymbolAddress((void**)&p_wo_h, g_wo_h);
    cudaGetSymbolAddress((void**)&p_wo_l, g_wo_l);

    cvt_hilo_k<<<(2048*512 + 255)/256, 256>>>(qkvw, p_wq_h, p_wq_l, 2048*512);
    cvt_hilo_k<<<(1024*512 + 255)/256, 256>>>(gw,   p_wg_h, p_wg_l, 1024*512);
    cvt_hilo_k<<<(512*1024 + 255)/256, 256>>>(ow,   p_wo_h, p_wo_l, 512*1024);

    conv_silu_k<<<MROWS, 512>>>(x, convw);

    gemm128_k<0><<<dim3(2048/128, MROWS/128), 256, GEMM_SMEM>>>(p_xs_h, p_xs_l, p_wq_h, p_wq_l, nullptr, p_qkv, 2048, 512);
    gemm128_k<1><<<dim3(1024/128, MROWS/128), 256, GEMM_SMEM>>>(p_xs_h, p_xs_l, p_wg_h, p_wg_l, gb, p_g, 1024, 512);

    gk1_k<<<MROWS/64, 256>>>(gkw1);
    gk2_k<<<dim3(4, MROWS/64), 256>>>(gkw2, gkb2);
    gla_k<<<dim3(4, BB*NH, 2), 256, GLA_SMEM_BYTES>>>();
    combine_k<<<BB*NH*NN, 256>>>(gnw, lnw);

    gemm128_k<0><<<dim3(512/128, MROWS/128), 256, GEMM_SMEM>>>(p_oc_h, p_oc_l, p_wo_h, p_wo_l, nullptr, out, 512, 1024);
}

// round 14
// speedup vs baseline: 1.1527x; 1.1527x over previous
#include <cuda_runtime.h>
#include <cuda_bf16.h>
#include <cuda_fp16.h>
#include <math.h>
#include <stdint.h>

// ---------------------------------------------------------------------------
// Problem constants
// ---------------------------------------------------------------------------
#define BB     8
#define NN     3136
#define HH_    56
#define WW_    56
#define DM     512
#define NH     4
#define HQ     128
#define HV     256
#define CH     64
#define NCH    49
#define MROWS  (BB*NN)       // 25088

// ---------------------------------------------------------------------------
// Scratch
// ---------------------------------------------------------------------------
static __device__ float g_xs   [MROWS*DM];
static __device__ __half g_xs_h[MROWS*DM];
static __device__ __half g_xs_l[MROWS*DM];
static __device__ float g_qkv  [MROWS*2048];
static __device__ float g_g    [MROWS*1024];
static __device__ float g_gklat[MROWS*16];
static __device__ float g_gk   [MROWS*1024];
static __device__ float g_of   [MROWS*1024];
static __device__ float g_ob   [MROWS*1024];
static __device__ __half g_oc_h[MROWS*1024];
static __device__ __half g_oc_l[MROWS*1024];
static __device__ __half g_wq_h[2048*512];
static __device__ __half g_wg_h[1024*512];
static __device__ __half g_wo_h[512*1024];

// ---------------------------------------------------------------------------
// fast exp on the FMA/ALU pipes (no MUFU)
// ---------------------------------------------------------------------------
__device__ __forceinline__ float fast_exp(float x) {
    float t = x * 1.4426950408889634f;
    float z = t + 12582912.0f;            // 1.5 * 2^23
    int   n = __float_as_int(z);
    float fr = t - (z - 12582912.0f);
    float p = 0.00015403530393381608f;
    p = fmaf(p, fr, 0.0013333558146428443f);
    p = fmaf(p, fr, 0.009618129107628477f);
    p = fmaf(p, fr, 0.05550410866482158f);
    p = fmaf(p, fr, 0.2402265069591007f);
    p = fmaf(p, fr, 0.6931471805599453f);
    p = fmaf(p, fr, 1.0f);
    return __int_as_float(__float_as_int(p) + (n << 23));
}
__device__ __forceinline__ float sigm(float x) {
    return __fdividef(1.f, 1.f + fast_exp(-x));
}

__device__ __forceinline__ uint32_t smem_u32(const void* p) {
    uint32_t a;
    asm("{ .reg .u64 t; cvta.to.shared.u64 t, %1; cvt.u32.u64 %0, t; }" : "=r"(a) : "l"(p));
    return a;
}
__device__ __forceinline__ void cp16(uint32_t dst, const void* src) {
    asm volatile("cp.async.cg.shared.global [%0], [%1], 16;" :: "r"(dst), "l"(src));
}
#define CP_COMMIT() asm volatile("cp.async.commit_group;" ::: "memory")
#define CP_WAIT0()  asm volatile("cp.async.wait_group 0;" ::: "memory")
#define CP_WAIT1()  asm volatile("cp.async.wait_group 1;" ::: "memory")

__device__ __forceinline__ void ldsm4(uint32_t* r, uint32_t addr) {
    asm volatile("ldmatrix.sync.aligned.m8n8.x4.shared.b16 {%0,%1,%2,%3}, [%4];"
        : "=r"(r[0]), "=r"(r[1]), "=r"(r[2]), "=r"(r[3]) : "r"(addr));
}
__device__ __forceinline__ void ldsm4t(uint32_t* r, uint32_t addr) {
    asm volatile("ldmatrix.sync.aligned.m8n8.x4.trans.shared.b16 {%0,%1,%2,%3}, [%4];"
        : "=r"(r[0]), "=r"(r[1]), "=r"(r[2]), "=r"(r[3]) : "r"(addr));
}
// bf16 mma (GLA)
__device__ __forceinline__ void mma16816(float* c, const uint32_t* a, uint32_t b0, uint32_t b1) {
    asm volatile("mma.sync.aligned.m16n8k16.row.col.f32.bf16.bf16.f32 "
        "{%0,%1,%2,%3}, {%4,%5,%6,%7}, {%8,%9}, {%0,%1,%2,%3};"
        : "+f"(c[0]), "+f"(c[1]), "+f"(c[2]), "+f"(c[3])
        : "r"(a[0]), "r"(a[1]), "r"(a[2]), "r"(a[3]), "r"(b0), "r"(b1));
}
// fp16 mma (GEMMs)
__device__ __forceinline__ void mma16816h(float* c, const uint32_t* a, uint32_t b0, uint32_t b1) {
    asm volatile("mma.sync.aligned.m16n8k16.row.col.f32.f16.f16.f32 "
        "{%0,%1,%2,%3}, {%4,%5,%6,%7}, {%8,%9}, {%0,%1,%2,%3};"
        : "+f"(c[0]), "+f"(c[1]), "+f"(c[2]), "+f"(c[3])
        : "r"(a[0]), "r"(a[1]), "r"(a[2]), "r"(a[3]), "r"(b0), "r"(b1));
}

__device__ __forceinline__ uint32_t packbf2(float a, float b) {
    __nv_bfloat162 t;
    t.x = __float2bfloat16(a);
    t.y = __float2bfloat16(b);
    return *(uint32_t*)&t;
}

extern __shared__ char s_dyn[];

// ---------------------------------------------------------------------------
// 1) depthwise 3x3 conv + SiLU, emit fp32 + fp16 hi/lo
// ---------------------------------------------------------------------------
__global__ void __launch_bounds__(512) conv_silu_k(const float* __restrict__ x,
                                                   const float* __restrict__ w)
{
    int bn = blockIdx.x;
    int b  = bn / NN, n = bn % NN;
    int y  = n / WW_, xx = n % WW_;
    int c  = threadIdx.x;
    float wr[9];
#pragma unroll
    for (int i = 0; i < 9; ++i) wr[i] = w[c*9 + i];
    float acc = 0.f;
#pragma unroll
    for (int ky = 0; ky < 3; ++ky) {
        int yy = y + ky - 1;
        if (yy < 0 || yy >= HH_) continue;
#pragma unroll
        for (int kx = 0; kx < 3; ++kx) {
            int xc = xx + kx - 1;
            if (xc < 0 || xc >= WW_) continue;
            acc += x[(b*NN + yy*WW_ + xc)*DM + c] * wr[ky*3 + kx];
        }
    }
    float r = acc * sigm(acc);
    g_xs[bn*DM + c] = r;
    __half h = __float2half(r);
    g_xs_h[bn*DM + c] = h;
    g_xs_l[bn*DM + c] = __float2half(r - __half2float(h));
}

// ---------------------------------------------------------------------------
// fp16 conversion for weights (hi only — 2-term scheme)
// ---------------------------------------------------------------------------
__global__ void __launch_bounds__(256) cvt_h_k(const float* __restrict__ s,
                                               __half* __restrict__ h, int n)
{
    int i = blockIdx.x*256 + threadIdx.x;
    if (i < n) h[i] = __float2half(s[i]);
}

// ---------------------------------------------------------------------------
// 2) fp16x2 GEMM (NT): C = (Ah+Al) . Bh^T ; fp32 accum, mma.sync m16n8k16
//    tile 128x128, K-chunk 64, double-buffered cp.async, 96KB smem -> 2 CTA/SM
// ---------------------------------------------------------------------------
#define GEMM_STAGE 49152                 // 3 tiles x 16KB
#define GEMM_SMEM  (2*GEMM_STAGE)

template<int EPI>
__global__ void __launch_bounds__(256, 2)
gemm128_k(const __half* __restrict__ Ah, const __half* __restrict__ Al,
          const __half* __restrict__ Bh,
          const float* __restrict__ bias, float* __restrict__ C, int Nc, int K)
{
    const int tid  = threadIdx.x;
    const int lane = tid & 31;
    const int wid  = tid >> 5;
    const int wm   = (wid & 3) * 32;
    const int wn   = (wid >> 2) * 64;
    const int n0 = blockIdx.x * 128, m0 = blockIdx.y * 128;
    const uint32_t sb = smem_u32(s_dyn);
    const int nk = K >> 6;

    float acc[2][8][4];
#pragma unroll
    for (int i = 0; i < 2; ++i)
#pragma unroll
        for (int j = 0; j < 8; ++j)
#pragma unroll
            for (int q = 0; q < 4; ++q) acc[i][j][q] = 0.f;

    auto load_chunk = [&](int kc) {
        uint32_t tb = sb + (kc & 1) * GEMM_STAGE;
        int kb = kc << 6;
#pragma unroll
        for (int it = 0; it < 4; ++it) {
            int i = tid + it*256;
            int row = i >> 3, seg = i & 7;
            uint32_t off = (uint32_t)(row*128 + seg*16);
            uint32_t sw = off ^ ((off >> 3) & 0x70);
            const __half* pAh = Ah + (size_t)(m0 + row)*K + kb + seg*8;
            const __half* pAl = Al + (size_t)(m0 + row)*K + kb + seg*8;
            const __half* pBh = Bh + (size_t)(n0 + row)*K + kb + seg*8;
            cp16(tb +         sw, pAh);
            cp16(tb + 16384 + sw, pAl);
            cp16(tb + 32768 + sw, pBh);
        }
    };

    load_chunk(0); CP_COMMIT();

    const int aRow = lane & 15;
    const int aKof = ((lane >> 4) & 1) * 16;
    const int bRowL = (lane & 7) + ((lane & 16) ? 8 : 0);
    const int bKof = (lane & 8) ? 16 : 0;

    for (int c = 0; c < nk; ++c) {
        if (c + 1 < nk) { load_chunk(c + 1); CP_COMMIT(); CP_WAIT1(); }
        else            { CP_WAIT0(); }
        __syncthreads();

        uint32_t tb = sb + (c & 1) * GEMM_STAGE;
#pragma unroll
        for (int ks = 0; ks < 4; ++ks) {
            const int kbyte = ks * 32;
            uint32_t aH[2][4], aL[2][4];
#pragma unroll
            for (int mt = 0; mt < 2; ++mt) {
                uint32_t off = (uint32_t)((wm + mt*16 + aRow) * 128 + kbyte + aKof);
                uint32_t sw = off ^ ((off >> 3) & 0x70);
                ldsm4(aH[mt], tb + sw);
                ldsm4(aL[mt], tb + 16384 + sw);
            }
#pragma unroll
            for (int ntp = 0; ntp < 4; ++ntp) {
                uint32_t off = (uint32_t)((wn + ntp*16 + bRowL) * 128 + kbyte + bKof);
                uint32_t sw = off ^ ((off >> 3) & 0x70);
                uint32_t bh[4];
                ldsm4(bh, tb + 32768 + sw);
#pragma unroll
                for (int mt = 0; mt < 2; ++mt) {
                    mma16816h(acc[mt][ntp*2+0], aH[mt], bh[0], bh[1]);
                    mma16816h(acc[mt][ntp*2+1], aH[mt], bh[2], bh[3]);
                    mma16816h(acc[mt][ntp*2+0], aL[mt], bh[0], bh[1]);
                    mma16816h(acc[mt][ntp*2+1], aL[mt], bh[2], bh[3]);
                }
            }
        }
        __syncthreads();
    }

    const int rbase = m0 + wm + (lane >> 2);
    const int cbase = n0 + wn + (lane & 3) * 2;
#pragma unroll
    for (int mt = 0; mt < 2; ++mt) {
#pragma unroll
        for (int nt = 0; nt < 8; ++nt) {
            int col = cbase + nt*8;
#pragma unroll
            for (int half = 0; half < 2; ++half) {
                int row = rbase + mt*16 + half*8;
                float v0 = acc[mt][nt][half*2+0];
                float v1 = acc[mt][nt][half*2+1];
                if (EPI == 1) {
                    v0 += bias[col+0]; v0 *= sigm(v0);
                    v1 += bias[col+1]; v1 *= sigm(v1);
                }
                float2 vv; vv.x = v0; vv.y = v1;
                *(float2*)&C[(size_t)row*Nc + col] = vv;
            }
        }
    }
}

// ---------------------------------------------------------------------------
// 3) gk low-rank stage 1
// ---------------------------------------------------------------------------
__global__ void __launch_bounds__(256) gk1_k(const float* __restrict__ w1)
{
    __shared__ float w1s[16*DM];
    int tid = threadIdx.x;
    for (int i = tid; i < 16*DM; i += 256) w1s[i] = w1[i];
    __syncthreads();
    int m0 = blockIdx.x * 64;
    int j  = tid & 15, rg = tid >> 4;
    const float* xb = &g_xs[(m0 + rg*4)*DM];
    const float4* w4 = (const float4*)&w1s[j*DM];
    float a0 = 0.f, a1 = 0.f, a2 = 0.f, a3 = 0.f;
#pragma unroll 4
    for (int k = 0; k < DM/4; ++k) {
        float4 wv = w4[k];
        float4 x0 = *(const float4*)&xb[0*DM + k*4];
        float4 x1 = *(const float4*)&xb[1*DM + k*4];
        float4 x2 = *(const float4*)&xb[2*DM + k*4];
        float4 x3 = *(const float4*)&xb[3*DM + k*4];
        a0 += x0.x*wv.x + x0.y*wv.y + x0.z*wv.z + x0.w*wv.w;
        a1 += x1.x*wv.x + x1.y*wv.y + x1.z*wv.z + x1.w*wv.w;
        a2 += x2.x*wv.x + x2.y*wv.y + x2.z*wv.z + x2.w*wv.w;
        a3 += x3.x*wv.x + x3.y*wv.y + x3.z*wv.z + x3.w*wv.w;
    }
    g_gklat[(m0+rg*4+0)*16 + j] = a0;
    g_gklat[(m0+rg*4+1)*16 + j] = a1;
    g_gklat[(m0+rg*4+2)*16 + j] = a2;
    g_gklat[(m0+rg*4+3)*16 + j] = a3;
}

// ---------------------------------------------------------------------------
// 4) gk stage 2
// ---------------------------------------------------------------------------
__global__ void __launch_bounds__(256) gk2_k(const float* __restrict__ w2,
                                             const float* __restrict__ b2)
{
    __shared__ float lat[64*16];
    int m0 = blockIdx.y * 64;
    int j  = blockIdx.x * 256 + threadIdx.x;
    for (int i = threadIdx.x; i < 64*16; i += 256) lat[i] = g_gklat[m0*16 + i];
    __syncthreads();
    float w[16];
#pragma unroll
    for (int i = 0; i < 16; ++i) w[i] = w2[j*16 + i];
    float bb = b2[j];
    for (int r = 0; r < 64; ++r) {
        float xv = bb;
#pragma unroll
        for (int i = 0; i < 16; ++i) xv += lat[r*16 + i]*w[i];
        float ls = fminf(xv, 0.f) - log1pf(fast_exp(-fabsf(xv)));
        g_gk[(m0+r)*1024 + j] = ls * (1.f/16.f);
    }
}

// ---------------------------------------------------------------------------
// 5) Chunked GLA — tensorized (mma.sync bf16x3; state fp32 in smem)
//    grid (vs 4, bh 32, dir 2), 256 threads = 8 warps (4m x 2n)
// ---------------------------------------------------------------------------
#define OF_SG    0
#define OF_EBT   33792
#define OF_SF    34304
#define OF_QEH   69120
#define OF_QEL   86528
#define OF_KDH   103936
#define OF_KDL   121344
#define OF_VH    138752
#define OF_VL    147968
#define OF_AH    157184
#define OF_AL    166400
#define OF_SBH   175616
#define OF_SBL   194048
#define GLA_SMEM_BYTES 212480

__global__ void __launch_bounds__(256, 1) gla_k()
{
    char* sm = s_dyn;
    const uint32_t sb = smem_u32(sm);
    float* sg  = (float*)(sm + OF_SG);
    float* ebt = (float*)(sm + OF_EBT);
    float* Sf  = (float*)(sm + OF_SF);

    const int vs  = blockIdx.x;
    const int bh  = blockIdx.y;
    const int dir = blockIdx.z;
    const int b   = bh >> 2;
    const int h   = bh & 3;
    const int tid = threadIdx.x;
    const int lane = tid & 31;
    const int w    = tid >> 5;
    const float scale = 0.088388347648318447f;  // 128^-0.5

    for (int i = tid; i < 128*68; i += 256) Sf[i] = 0.f;
    __syncthreads();

    const int qoff = h*HQ;
    const int koff = 512 + h*HQ;
    const int voff = 1024 + h*HV + vs*64;
    const int goff = dir*512 + h*HQ;
    const int rowb = b*NN;
    float* const outp = dir ? g_ob : g_of;

    const int m0w = (w & 3) * 16;
    const int n0w = (w >> 2) * 32;
    const int m0u = (w & 3) * 32;
    const int aRow = lane & 15;
    const int aSel = ((lane >> 4) & 1) * 16;
    const int bRowL = (lane & 7) + ((lane & 16) ? 8 : 0);
    const int bKof  = (lane & 8) ? 16 : 0;
    const int vRow = (lane & 7) + ((lane >> 3) & 1) * 8;
    const int vSel = ((lane >> 4) & 1) * 16;
    const int tRowT = (lane & 7) + ((lane >> 4) & 1) * 8;
    const int tSelT = ((lane >> 3) & 1) * 16;
    const int g8 = lane >> 2;
    const int q2 = (lane & 3) * 2;

    for (int c = 0; c < NCH; ++c) {
        // ---- P0: load gk chunk -> sg (f32); load+convert v -> v_h/v_l ----
#pragma unroll
        for (int it = 0; it < 8; ++it) {
            int j = tid + it*256;
            int t = j >> 5, d4 = (j & 31) * 4;
            int tg = dir ? (NN-1 - (c*64 + t)) : (c*64 + t);
            *(float4*)&sg[t*132 + d4] = *(const float4*)&g_gk[(size_t)(rowb+tg)*1024 + goff + d4];
        }
#pragma unroll
        for (int it = 0; it < 4; ++it) {
            int j = tid + it*256;
            int s = j >> 4, c4 = (j & 15) * 4;
            int tg = dir ? (NN-1 - (c*64 + s)) : (c*64 + s);
            float4 vv = *(const float4*)&g_qkv[(size_t)(rowb+tg)*2048 + voff + c4];
            __nv_bfloat16 h0 = __float2bfloat16(vv.x), h1 = __float2bfloat16(vv.y);
            __nv_bfloat16 h2 = __float2bfloat16(vv.z), h3 = __float2bfloat16(vv.w);
            uint2 hw, lw;
            hw.x = packbf2(vv.x, vv.y); hw.y = packbf2(vv.z, vv.w);
            lw.x = packbf2(vv.x - __bfloat162float(h0), vv.y - __bfloat162float(h1));
            lw.y = packbf2(vv.z - __bfloat162float(h2), vv.w - __bfloat162float(h3));
            *(uint2*)(sm + OF_VH + s*144 + c4*2) = hw;
            *(uint2*)(sm + OF_VL + s*144 + c4*2) = lw;
        }
        __syncthreads();

        // ---- P1: cumsum along t ----
        if (tid < 128) {
            int d = tid;
            float run = 0.f;
#pragma unroll
            for (int blk = 0; blk < 4; ++blk) {
                float r[16];
#pragma unroll
                for (int i = 0; i < 16; ++i) r[i] = sg[(blk*16+i)*132 + d];
#pragma unroll
                for (int i = 0; i < 16; ++i) { run += r[i]; r[i] = run; }
#pragma unroll
                for (int i = 0; i < 16; ++i) sg[(blk*16+i)*132 + d] = r[i];
            }
            ebt[d] = fast_exp(run);
        }
        __syncthreads();

        // ---- P2: qe/kd conversion + S -> bf16 split ----
#pragma unroll
        for (int it = 0; it < 8; ++it) {
            int j = tid + it*256;
            int t = j >> 5, d4 = (j & 31) * 4;
            int tg = dir ? (NN-1 - (c*64 + t)) : (c*64 + t);
            size_t r = (size_t)(rowb+tg)*2048;
            float4 qv = *(const float4*)&g_qkv[r + qoff + d4];
            float4 kv = *(const float4*)&g_qkv[r + koff + d4];
            float4 bv = *(float4*)&sg[t*132 + d4];
            float e0 = fast_exp(bv.x), e1 = fast_exp(bv.y), e2 = fast_exp(bv.z), e3 = fast_exp(bv.w);
            float f0 = fast_exp(-bv.x), f1 = fast_exp(-bv.y), f2 = fast_exp(-bv.z), f3 = fast_exp(-bv.w);
            float q0 = qv.x*e0*scale, q1 = qv.y*e1*scale, q2v = qv.z*e2*scale, q3 = qv.w*e3*scale;
            float k0 = kv.x*f0, k1 = kv.y*f1, k2 = kv.z*f2, k3 = kv.w*f3;
            __nv_bfloat16 qh0 = __float2bfloat16(q0), qh1 = __float2bfloat16(q1);
            __nv_bfloat16 qh2 = __float2bfloat16(q2v), qh3 = __float2bfloat16(q3);
            __nv_bfloat16 kh0 = __float2bfloat16(k0), kh1 = __float2bfloat16(k1);
            __nv_bfloat16 kh2 = __float2bfloat16(k2), kh3 = __float2bfloat16(k3);
            uint2 qhw, qlw, khw, klw;
            qhw.x = packbf2(q0, q1); qhw.y = packbf2(q2v, q3);
            qlw.x = packbf2(q0 - __bfloat162float(qh0), q1 - __bfloat162float(qh1));
            qlw.y = packbf2(q2v - __bfloat162float(qh2), q3 - __bfloat162float(qh3));
            khw.x = packbf2(k0, k1); khw.y = packbf2(k2, k3);
            klw.x = packbf2(k0 - __bfloat162float(kh0), k1 - __bfloat162float(kh1));
            klw.y = packbf2(k2 - __bfloat162float(kh2), k3 - __bfloat162float(kh3));
            *(uint2*)(sm + OF_QEH + t*272 + d4*2) = qhw;
            *(uint2*)(sm + OF_QEL + t*272 + d4*2) = qlw;
            *(uint2*)(sm + OF_KDH + t*272 + d4*2) = khw;
            *(uint2*)(sm + OF_KDL + t*272 + d4*2) = klw;
        }
#pragma unroll
        for (int it = 0; it < 16; ++it) {
            int j = tid + it*256;
            int d = j >> 5, c2 = (j & 31) * 2;
            float2 sv = *(float2*)&Sf[d*68 + c2];
            __nv_bfloat16 s0 = __float2bfloat16(sv.x), s1 = __float2bfloat16(sv.y);
            *(uint32_t*)(sm + OF_SBH + d*144 + c2*2) = packbf2(sv.x, sv.y);
            *(uint32_t*)(sm + OF_SBL + d*144 + c2*2) =
                packbf2(sv.x - __bfloat162float(s0), sv.y - __bfloat162float(s1));
        }
        __syncthreads();

        // ---- P3: A = qe @ kd^T (64x64, k=128), mask, store bf16 hi/lo ----
        {
            float acc[4][4];
#pragma unroll
            for (int f = 0; f < 4; ++f)
#pragma unroll
                for (int j = 0; j < 4; ++j) acc[f][j] = 0.f;
#pragma unroll
            for (int ks = 0; ks < 8; ++ks) {
                int kb = ks * 32;
                uint32_t aH[4], aL[4];
                ldsm4(aH, sb + OF_QEH + (m0w + aRow)*272 + kb + aSel);
                ldsm4(aL, sb + OF_QEL + (m0w + aRow)*272 + kb + aSel);
                uint32_t bh0[4], bh1[4], bl0[4], bl1[4];
                ldsm4(bh0, sb + OF_KDH + (n0w + bRowL)*272 + kb + bKof);
                ldsm4(bh1, sb + OF_KDH + (n0w + 16 + bRowL)*272 + kb + bKof);
                ldsm4(bl0, sb + OF_KDL + (n0w + bRowL)*272 + kb + bKof);
                ldsm4(bl1, sb + OF_KDL + (n0w + 16 + bRowL)*272 + kb + bKof);
                mma16816(acc[0], aH, bh0[0], bh0[1]);
                mma16816(acc[1], aH, bh0[2], bh0[3]);
                mma16816(acc[2], aH, bh1[0], bh1[1]);
                mma16816(acc[3], aH, bh1[2], bh1[3]);
                mma16816(acc[0], aH, bl0[0], bl0[1]);
                mma16816(acc[1], aH, bl0[2], bl0[3]);
                mma16816(acc[2], aH, bl1[0], bl1[1]);
                mma16816(acc[3], aH, bl1[2], bl1[3]);
                mma16816(acc[0], aL, bh0[0], bh0[1]);
                mma16816(acc[1], aL, bh0[2], bh0[3]);
                mma16816(acc[2], aL, bh1[0], bh1[1]);
                mma16816(acc[3], aL, bh1[2], bh1[3]);
            }
#pragma unroll
            for (int f = 0; f < 4; ++f) {
                int scol = n0w + f*8 + q2;
#pragma unroll
                for (int hh = 0; hh < 2; ++hh) {
                    int t = m0w + g8 + hh*8;
                    float v0 = (scol     <= t) ? acc[f][hh*2+0] : 0.f;
                    float v1 = (scol + 1 <= t) ? acc[f][hh*2+1] : 0.f;
                    __nv_bfloat16 a0 = __float2bfloat16(v0), a1 = __float2bfloat16(v1);
                    *(uint32_t*)(sm + OF_AH + t*144 + scol*2) = packbf2(v0, v1);
                    *(uint32_t*)(sm + OF_AL + t*144 + scol*2) =
                        packbf2(v0 - __bfloat162float(a0), v1 - __bfloat162float(a1));
                }
            }
        }
        __syncthreads();

        // ---- P4: o = A@v + qe@S -> gmem ; U = kd^T @ v ; S update ----
        {
            float acc[4][4];
#pragma unroll
            for (int f = 0; f < 4; ++f)
#pragma unroll
                for (int j = 0; j < 4; ++j) acc[f][j] = 0.f;
            // A @ v  (k = s = 64)
#pragma unroll
            for (int ks = 0; ks < 4; ++ks) {
                int kb = ks * 32;
                uint32_t aH[4], aL[4];
                ldsm4(aH, sb + OF_AH + (m0w + aRow)*144 + kb + aSel);
                ldsm4(aL, sb + OF_AL + (m0w + aRow)*144 + kb + aSel);
                uint32_t b0h[4], b1h[4], b0l[4], b1l[4];
                uint32_t vr = (ks*16 + vRow)*144;
                ldsm4t(b0h, sb + OF_VH + vr + n0w*2 + vSel);
                ldsm4t(b1h, sb + OF_VH + vr + (n0w + 16)*2 + vSel);
                ldsm4t(b0l, sb + OF_VL + vr + n0w*2 + vSel);
                ldsm4t(b1l, sb + OF_VL + vr + (n0w + 16)*2 + vSel);
                mma16816(acc[0], aH, b0h[0], b0h[1]);
                mma16816(acc[1], aH, b0h[2], b0h[3]);
                mma16816(acc[2], aH, b1h[0], b1h[1]);
                mma16816(acc[3], aH, b1h[2], b1h[3]);
                mma16816(acc[0], aH, b0l[0], b0l[1]);
                mma16816(acc[1], aH, b0l[2], b0l[3]);
                mma16816(acc[2], aH, b1l[0], b1l[1]);
                mma16816(acc[3], aH, b1l[2], b1l[3]);
                mma16816(acc[0], aL, b0h[0], b0h[1]);
                mma16816(acc[1], aL, b0h[2], b0h[3]);
                mma16816(acc[2], aL, b1h[0], b1h[1]);
                mma16816(acc[3], aL, b1h[2], b1h[3]);
            }
            // qe @ S  (k = d = 128)
#pragma unroll
            for (int ks = 0; ks < 8; ++ks) {
                int kb = ks * 32;
                uint32_t aH[4], aL[4];
                ldsm4(aH, sb + OF_QEH + (m0w + aRow)*272 + kb + aSel);
                ldsm4(aL, sb + OF_QEL + (m0w + aRow)*272 + kb + aSel);
                uint32_t b0h[4], b1h[4], b0l[4], b1l[4];
                uint32_t sr = (ks*16 + vRow)*144;
                ldsm4t(b0h, sb + OF_SBH + sr + n0w*2 + vSel);
                ldsm4t(b1h, sb + OF_SBH + sr + (n0w + 16)*2 + vSel);
                ldsm4t(b0l, sb + OF_SBL + sr + n0w*2 + vSel);
                ldsm4t(b1l, sb + OF_SBL + sr + (n0w + 16)*2 + vSel);
                mma16816(acc[0], aH, b0h[0], b0h[1]);
                mma16816(acc[1], aH, b0h[2], b0h[3]);
                mma16816(acc[2], aH, b1h[0], b1h[1]);
                mma16816(acc[3], aH, b1h[2], b1h[3]);
                mma16816(acc[0], aH, b0l[0], b0l[1]);
                mma16816(acc[1], aH, b0l[2], b0l[3]);
                mma16816(acc[2], aH, b1l[0], b1l[1]);
                mma16816(acc[3], aH, b1l[2], b1l[3]);
                mma16816(acc[0], aL, b0h[0], b0h[1]);
                mma16816(acc[1], aL, b0h[2], b0h[3]);
                mma16816(acc[2], aL, b1h[0], b1h[1]);
                mma16816(acc[3], aL, b1h[2], b1h[3]);
            }
            // write o
#pragma unroll
            for (int f = 0; f < 4; ++f) {
                int col = n0w + f*8 + q2;
#pragma unroll
                for (int hh = 0; hh < 2; ++hh) {
                    int t = m0w + g8 + hh*8;
                    int tg = dir ? (NN-1 - (c*64 + t)) : (c*64 + t);
                    float2 vv; vv.x = acc[f][hh*2+0]; vv.y = acc[f][hh*2+1];
                    *(float2*)&outp[(size_t)(bh*NN + tg)*256 + vs*64 + col] = vv;
                }
            }
            // U = kd^T @ v  (128x64, k=t=64)
            float au[2][4][4];
#pragma unroll
            for (int mt = 0; mt < 2; ++mt)
#pragma unroll
                for (int f = 0; f < 4; ++f)
#pragma unroll
                    for (int j = 0; j < 4; ++j) au[mt][f][j] = 0.f;
#pragma unroll
            for (int ks = 0; ks < 4; ++ks) {
                uint32_t aTh[2][4], aTl[2][4];
                uint32_t tr = (ks*16 + tRowT)*272;
#pragma unroll
                for (int mt = 0; mt < 2; ++mt) {
                    uint32_t dby = (m0u + mt*16)*2 + tSelT;
                    ldsm4t(aTh[mt], sb + OF_KDH + tr + dby);
                    ldsm4t(aTl[mt], sb + OF_KDL + tr + dby);
                }
                uint32_t b0h[4], b1h[4], b0l[4], b1l[4];
                uint32_t vr = (ks*16 + vRow)*144;
                ldsm4t(b0h, sb + OF_VH + vr + n0w*2 + vSel);
                ldsm4t(b1h, sb + OF_VH + vr + (n0w + 16)*2 + vSel);
                ldsm4t(b0l, sb + OF_VL + vr + n0w*2 + vSel);
                ldsm4t(b1l, sb + OF_VL + vr + (n0w + 16)*2 + vSel);
#pragma unroll
                for (int mt = 0; mt < 2; ++mt) {
                    mma16816(au[mt][0], aTh[mt], b0h[0], b0h[1]);
                    mma16816(au[mt][1], aTh[mt], b0h[2], b0h[3]);
                    mma16816(au[mt][2], aTh[mt], b1h[0], b1h[1]);
                    mma16816(au[mt][3], aTh[mt], b1h[2], b1h[3]);
                    mma16816(au[mt][0], aTh[mt], b0l[0], b0l[1]);
                    mma16816(au[mt][1], aTh[mt], b0l[2], b0l[3]);
                    mma16816(au[mt][2], aTh[mt], b1l[0], b1l[1]);
                    mma16816(au[mt][3], aTh[mt], b1l[2], b1l[3]);
                    mma16816(au[mt][0], aTl[mt], b0h[0], b0h[1]);
                    mma16816(au[mt][1], aTl[mt], b0h[2], b0h[3]);
                    mma16816(au[mt][2], aTl[mt], b1h[0], b1h[1]);
                    mma16816(au[mt][3], aTl[mt], b1h[2], b1h[3]);
                }
            }
            // S = exp(btot) * (S + U)
#pragma unroll
            for (int mt = 0; mt < 2; ++mt) {
#pragma unroll
                for (int f = 0; f < 4; ++f) {
                    int vc = n0w + f*8 + q2;
#pragma unroll
                    for (int hh = 0; hh < 2; ++hh) {
                        int d = m0u + mt*16 + g8 + hh*8;
                        float e = ebt[d];
                        float2 s = *(float2*)&Sf[d*68 + vc];
                        s.x = e * (s.x + au[mt][f][hh*2+0]);
                        s.y = e * (s.y + au[mt][f][hh*2+1]);
                        *(float2*)&Sf[d*68 + vc] = s;
                    }
                }
            }
        }
        __syncthreads();
    }
}

// ---------------------------------------------------------------------------
// 6) combine -> fp16 hi/lo for the output GEMM
// ---------------------------------------------------------------------------
__global__ void __launch_bounds__(256) combine_k(const float* __restrict__ gnw,
                                                 const float* __restrict__ lnw)
{
    __shared__ float red[16];
    int idx = blockIdx.x;
    int bh  = idx / NN, t = idx % NN;
    int b   = bh >> 2,  h = bh & 3;
    int v   = threadIdx.x;
    float of = g_of[(size_t)idx*256 + v];
    float ob = g_ob[(size_t)idx*256 + v];
    float sf = of*of, sb = ob*ob;
#pragma unroll
    for (int o = 16; o > 0; o >>= 1) {
        sf += __shfl_xor_sync(0xffffffffu, sf, o);
        sb += __shfl_xor_sync(0xffffffffu, sb, o);
    }
    int w = v >> 5, l = v & 31;
    if (l == 0) { red[w] = sf; red[8+w] = sb; }
    __syncthreads();
    float tf = 0.f, tb = 0.f;
#pragma unroll
    for (int i = 0; i < 8; ++i) { tf += red[i]; tb += red[8+i]; }
    float inf_ = rsqrtf(tf*(1.f/256.f) + 1e-5f);
    float inb_ = rsqrtf(tb*(1.f/256.f) + 1e-5f);
    float o = of*inf_*gnw[v] + ob*inb_*lnw[v];
    int gi = (b*NN + t)*1024 + h*256 + v;
    float val = o * g_g[gi];
    __half hh = __float2half(val);
    g_oc_h[gi] = hh;
    g_oc_l[gi] = __float2half(val - __half2float(hh));
}

// ---------------------------------------------------------------------------
// launcher
// ---------------------------------------------------------------------------
extern "C" void kernel_launch(void* const* d_in, const int* in_sizes, int n_in,
                              void* d_out, int out_size)
{
    const float* x     = (const float*)d_in[0];
    const float* convw = (const float*)d_in[1];
    const float* qkvw  = (const float*)d_in[2];
    const float* gkw1  = (const float*)d_in[3];
    const float* gkw2  = (const float*)d_in[4];
    const float* gkb2  = (const float*)d_in[5];
    const float* gw    = (const float*)d_in[6];
    const float* gb    = (const float*)d_in[7];
    const float* gnw   = (const float*)d_in[8];
    const float* lnw   = (const float*)d_in[9];
    const float* ow    = (const float*)d_in[10];
    float* out = (float*)d_out;

    cudaFuncSetAttribute(gla_k, cudaFuncAttributeMaxDynamicSharedMemorySize, GLA_SMEM_BYTES);
    cudaFuncSetAttribute(gemm128_k<0>, cudaFuncAttributeMaxDynamicSharedMemorySize, GEMM_SMEM);
    cudaFuncSetAttribute(gemm128_k<1>, cudaFuncAttributeMaxDynamicSharedMemorySize, GEMM_SMEM);

    float *p_qkv, *p_g;
    __half *p_xs_h, *p_xs_l, *p_oc_h, *p_oc_l;
    __half *p_wq_h, *p_wg_h, *p_wo_h;
    cudaGetSymbolAddress((void**)&p_qkv,  g_qkv);
    cudaGetSymbolAddress((void**)&p_g,    g_g);
    cudaGetSymbolAddress((void**)&p_xs_h, g_xs_h);
    cudaGetSymbolAddress((void**)&p_xs_l, g_xs_l);
    cudaGetSymbolAddress((void**)&p_oc_h, g_oc_h);
    cudaGetSymbolAddress((void**)&p_oc_l, g_oc_l);
    cudaGetSymbolAddress((void**)&p_wq_h, g_wq_h);
    cudaGetSymbolAddress((void**)&p_wg_h, g_wg_h);
    cudaGetSymbolAddress((void**)&p_wo_h, g_wo_h);

    cvt_h_k<<<(2048*512 + 255)/256, 256>>>(qkvw, p_wq_h, 2048*512);
    cvt_h_k<<<(1024*512 + 255)/256, 256>>>(gw,   p_wg_h, 1024*512);
    cvt_h_k<<<(512*1024 + 255)/256, 256>>>(ow,   p_wo_h, 512*1024);

    conv_silu_k<<<MROWS, 512>>>(x, convw);

    gemm128_k<0><<<dim3(2048/128, MROWS/128), 256, GEMM_SMEM>>>(p_xs_h, p_xs_l, p_wq_h, nullptr, p_qkv, 2048, 512);
    gemm128_k<1><<<dim3(1024/128, MROWS/128), 256, GEMM_SMEM>>>(p_xs_h, p_xs_l, p_wg_h, gb, p_g, 1024, 512);

    gk1_k<<<MROWS/64, 256>>>(gkw1);
    gk2_k<<<dim3(4, MROWS/64), 256>>>(gkw2, gkb2);
    gla_k<<<dim3(4, BB*NH, 2), 256, GLA_SMEM_BYTES>>>();
    combine_k<<<BB*NH*NN, 256>>>(gnw, lnw);

    gemm128_k<0><<<dim3(512/128, MROWS/128), 256, GEMM_SMEM>>>(p_oc_h, p_oc_l, p_wo_h, nullptr, out, 512, 1024);
}

// round 15
// speedup vs baseline: 1.4451x; 1.2538x over previous
#include <cuda_runtime.h>
#include <cuda_bf16.h>
#include <cuda_fp16.h>
#include <math.h>
#include <stdint.h>

// ---------------------------------------------------------------------------
// Problem constants
// ---------------------------------------------------------------------------
#define BB     8
#define NN     3136
#define HH_    56
#define WW_    56
#define DM     512
#define NH     4
#define HQ     128
#define HV     256
#define CH     64
#define NCH    49
#define MROWS  (BB*NN)       // 25088

// ---------------------------------------------------------------------------
// Scratch
// ---------------------------------------------------------------------------
static __device__ float g_xs   [MROWS*DM];
static __device__ __half g_xs_h[MROWS*DM];
static __device__ __half g_xs_l[MROWS*DM];
static __device__ float g_qkv  [MROWS*2048];
static __device__ float g_g    [MROWS*1024];
static __device__ float g_gklat[MROWS*16];
static __device__ float g_gk   [MROWS*1024];
static __device__ float g_of   [MROWS*1024];
static __device__ float g_ob   [MROWS*1024];
static __device__ __half g_oc_h[MROWS*1024];
static __device__ __half g_oc_l[MROWS*1024];
static __device__ __half g_wq_h[2048*512];
static __device__ __half g_wg_h[1024*512];
static __device__ __half g_wo_h[512*1024];

// ---------------------------------------------------------------------------
// fast exp on the FMA/ALU pipes (no MUFU)
// ---------------------------------------------------------------------------
__device__ __forceinline__ float fast_exp(float x) {
    float t = x * 1.4426950408889634f;
    float z = t + 12582912.0f;            // 1.5 * 2^23
    int   n = __float_as_int(z);
    float fr = t - (z - 12582912.0f);
    float p = 0.00015403530393381608f;
    p = fmaf(p, fr, 0.0013333558146428443f);
    p = fmaf(p, fr, 0.009618129107628477f);
    p = fmaf(p, fr, 0.05550410866482158f);
    p = fmaf(p, fr, 0.2402265069591007f);
    p = fmaf(p, fr, 0.6931471805599453f);
    p = fmaf(p, fr, 1.0f);
    return __int_as_float(__float_as_int(p) + (n << 23));
}
__device__ __forceinline__ float sigm(float x) {
    return __fdividef(1.f, 1.f + fast_exp(-x));
}

__device__ __forceinline__ uint32_t smem_u32(const void* p) {
    uint32_t a;
    asm("{ .reg .u64 t; cvta.to.shared.u64 t, %1; cvt.u32.u64 %0, t; }" : "=r"(a) : "l"(p));
    return a;
}
__device__ __forceinline__ void cp16(uint32_t dst, const void* src) {
    asm volatile("cp.async.cg.shared.global [%0], [%1], 16;" :: "r"(dst), "l"(src));
}
#define CP_COMMIT() asm volatile("cp.async.commit_group;" ::: "memory")
#define CP_WAIT0()  asm volatile("cp.async.wait_group 0;" ::: "memory")
#define CP_WAIT1()  asm volatile("cp.async.wait_group 1;" ::: "memory")

__device__ __forceinline__ void ldsm4(uint32_t* r, uint32_t addr) {
    asm volatile("ldmatrix.sync.aligned.m8n8.x4.shared.b16 {%0,%1,%2,%3}, [%4];"
        : "=r"(r[0]), "=r"(r[1]), "=r"(r[2]), "=r"(r[3]) : "r"(addr));
}
__device__ __forceinline__ void ldsm4t(uint32_t* r, uint32_t addr) {
    asm volatile("ldmatrix.sync.aligned.m8n8.x4.trans.shared.b16 {%0,%1,%2,%3}, [%4];"
        : "=r"(r[0]), "=r"(r[1]), "=r"(r[2]), "=r"(r[3]) : "r"(addr));
}
// bf16 mma (GLA)
__device__ __forceinline__ void mma16816(float* c, const uint32_t* a, uint32_t b0, uint32_t b1) {
    asm volatile("mma.sync.aligned.m16n8k16.row.col.f32.bf16.bf16.f32 "
        "{%0,%1,%2,%3}, {%4,%5,%6,%7}, {%8,%9}, {%0,%1,%2,%3};"
        : "+f"(c[0]), "+f"(c[1]), "+f"(c[2]), "+f"(c[3])
        : "r"(a[0]), "r"(a[1]), "r"(a[2]), "r"(a[3]), "r"(b0), "r"(b1));
}
// fp16 mma (GEMMs)
__device__ __forceinline__ void mma16816h(float* c, const uint32_t* a, uint32_t b0, uint32_t b1) {
    asm volatile("mma.sync.aligned.m16n8k16.row.col.f32.f16.f16.f32 "
        "{%0,%1,%2,%3}, {%4,%5,%6,%7}, {%8,%9}, {%0,%1,%2,%3};"
        : "+f"(c[0]), "+f"(c[1]), "+f"(c[2]), "+f"(c[3])
        : "r"(a[0]), "r"(a[1]), "r"(a[2]), "r"(a[3]), "r"(b0), "r"(b1));
}

__device__ __forceinline__ uint32_t packbf2(float a, float b) {
    __nv_bfloat162 t;
    t.x = __float2bfloat16(a);
    t.y = __float2bfloat16(b);
    return *(uint32_t*)&t;
}

extern __shared__ char s_dyn[];

// ---------------------------------------------------------------------------
// 1) depthwise 3x3 conv + SiLU, emit fp32 + fp16 hi/lo
// ---------------------------------------------------------------------------
__global__ void __launch_bounds__(512) conv_silu_k(const float* __restrict__ x,
                                                   const float* __restrict__ w)
{
    int bn = blockIdx.x;
    int b  = bn / NN, n = bn % NN;
    int y  = n / WW_, xx = n % WW_;
    int c  = threadIdx.x;
    float wr[9];
#pragma unroll
    for (int i = 0; i < 9; ++i) wr[i] = w[c*9 + i];
    float acc = 0.f;
#pragma unroll
    for (int ky = 0; ky < 3; ++ky) {
        int yy = y + ky - 1;
        if (yy < 0 || yy >= HH_) continue;
#pragma unroll
        for (int kx = 0; kx < 3; ++kx) {
            int xc = xx + kx - 1;
            if (xc < 0 || xc >= WW_) continue;
            acc += x[(b*NN + yy*WW_ + xc)*DM + c] * wr[ky*3 + kx];
        }
    }
    float r = acc * sigm(acc);
    g_xs[bn*DM + c] = r;
    __half h = __float2half(r);
    g_xs_h[bn*DM + c] = h;
    g_xs_l[bn*DM + c] = __float2half(r - __half2float(h));
}

// ---------------------------------------------------------------------------
// fp16 conversion for weights (hi only — 2-term scheme)
// ---------------------------------------------------------------------------
__global__ void __launch_bounds__(256) cvt_h_k(const float* __restrict__ s,
                                               __half* __restrict__ h, int n)
{
    int i = blockIdx.x*256 + threadIdx.x;
    if (i < n) h[i] = __float2half(s[i]);
}

// ---------------------------------------------------------------------------
// 2) fp16x2 GEMM (NT): C = (Ah+Al) . Bh^T ; fp32 accum, mma.sync m16n8k16
// ---------------------------------------------------------------------------
#define GEMM_STAGE 49152
#define GEMM_SMEM  (2*GEMM_STAGE)

template<int EPI>
__global__ void __launch_bounds__(256, 2)
gemm128_k(const __half* __restrict__ Ah, const __half* __restrict__ Al,
          const __half* __restrict__ Bh,
          const float* __restrict__ bias, float* __restrict__ C, int Nc, int K)
{
    const int tid  = threadIdx.x;
    const int lane = tid & 31;
    const int wid  = tid >> 5;
    const int wm   = (wid & 3) * 32;
    const int wn   = (wid >> 2) * 64;
    const int n0 = blockIdx.x * 128, m0 = blockIdx.y * 128;
    const uint32_t sb = smem_u32(s_dyn);
    const int nk = K >> 6;

    float acc[2][8][4];
#pragma unroll
    for (int i = 0; i < 2; ++i)
#pragma unroll
        for (int j = 0; j < 8; ++j)
#pragma unroll
            for (int q = 0; q < 4; ++q) acc[i][j][q] = 0.f;

    auto load_chunk = [&](int kc) {
        uint32_t tb = sb + (kc & 1) * GEMM_STAGE;
        int kb = kc << 6;
#pragma unroll
        for (int it = 0; it < 4; ++it) {
            int i = tid + it*256;
            int row = i >> 3, seg = i & 7;
            uint32_t off = (uint32_t)(row*128 + seg*16);
            uint32_t sw = off ^ ((off >> 3) & 0x70);
            const __half* pAh = Ah + (size_t)(m0 + row)*K + kb + seg*8;
            const __half* pAl = Al + (size_t)(m0 + row)*K + kb + seg*8;
            const __half* pBh = Bh + (size_t)(n0 + row)*K + kb + seg*8;
            cp16(tb +         sw, pAh);
            cp16(tb + 16384 + sw, pAl);
            cp16(tb + 32768 + sw, pBh);
        }
    };

    load_chunk(0); CP_COMMIT();

    const int aRow = lane & 15;
    const int aKof = ((lane >> 4) & 1) * 16;
    const int bRowL = (lane & 7) + ((lane & 16) ? 8 : 0);
    const int bKof = (lane & 8) ? 16 : 0;

    for (int c = 0; c < nk; ++c) {
        if (c + 1 < nk) { load_chunk(c + 1); CP_COMMIT(); CP_WAIT1(); }
        else            { CP_WAIT0(); }
        __syncthreads();

        uint32_t tb = sb + (c & 1) * GEMM_STAGE;
#pragma unroll
        for (int ks = 0; ks < 4; ++ks) {
            const int kbyte = ks * 32;
            uint32_t aH[2][4], aL[2][4];
#pragma unroll
            for (int mt = 0; mt < 2; ++mt) {
                uint32_t off = (uint32_t)((wm + mt*16 + aRow) * 128 + kbyte + aKof);
                uint32_t sw = off ^ ((off >> 3) & 0x70);
                ldsm4(aH[mt], tb + sw);
                ldsm4(aL[mt], tb + 16384 + sw);
            }
#pragma unroll
            for (int ntp = 0; ntp < 4; ++ntp) {
                uint32_t off = (uint32_t)((wn + ntp*16 + bRowL) * 128 + kbyte + bKof);
                uint32_t sw = off ^ ((off >> 3) & 0x70);
                uint32_t bh[4];
                ldsm4(bh, tb + 32768 + sw);
#pragma unroll
                for (int mt = 0; mt < 2; ++mt) {
                    mma16816h(acc[mt][ntp*2+0], aH[mt], bh[0], bh[1]);
                    mma16816h(acc[mt][ntp*2+1], aH[mt], bh[2], bh[3]);
                    mma16816h(acc[mt][ntp*2+0], aL[mt], bh[0], bh[1]);
                    mma16816h(acc[mt][ntp*2+1], aL[mt], bh[2], bh[3]);
                }
            }
        }
        __syncthreads();
    }

    const int rbase = m0 + wm + (lane >> 2);
    const int cbase = n0 + wn + (lane & 3) * 2;
#pragma unroll
    for (int mt = 0; mt < 2; ++mt) {
#pragma unroll
        for (int nt = 0; nt < 8; ++nt) {
            int col = cbase + nt*8;
#pragma unroll
            for (int half = 0; half < 2; ++half) {
                int row = rbase + mt*16 + half*8;
                float v0 = acc[mt][nt][half*2+0];
                float v1 = acc[mt][nt][half*2+1];
                if (EPI == 1) {
                    v0 += bias[col+0]; v0 *= sigm(v0);
                    v1 += bias[col+1]; v1 *= sigm(v1);
                }
                float2 vv; vv.x = v0; vv.y = v1;
                *(float2*)&C[(size_t)row*Nc + col] = vv;
            }
        }
    }
}

// ---------------------------------------------------------------------------
// 3) gk low-rank stage 1
// ---------------------------------------------------------------------------
__global__ void __launch_bounds__(256) gk1_k(const float* __restrict__ w1)
{
    __shared__ float w1s[16*DM];
    int tid = threadIdx.x;
    for (int i = tid; i < 16*DM; i += 256) w1s[i] = w1[i];
    __syncthreads();
    int m0 = blockIdx.x * 64;
    int j  = tid & 15, rg = tid >> 4;
    const float* xb = &g_xs[(m0 + rg*4)*DM];
    const float4* w4 = (const float4*)&w1s[j*DM];
    float a0 = 0.f, a1 = 0.f, a2 = 0.f, a3 = 0.f;
#pragma unroll 4
    for (int k = 0; k < DM/4; ++k) {
        float4 wv = w4[k];
        float4 x0 = *(const float4*)&xb[0*DM + k*4];
        float4 x1 = *(const float4*)&xb[1*DM + k*4];
        float4 x2 = *(const float4*)&xb[2*DM + k*4];
        float4 x3 = *(const float4*)&xb[3*DM + k*4];
        a0 += x0.x*wv.x + x0.y*wv.y + x0.z*wv.z + x0.w*wv.w;
        a1 += x1.x*wv.x + x1.y*wv.y + x1.z*wv.z + x1.w*wv.w;
        a2 += x2.x*wv.x + x2.y*wv.y + x2.z*wv.z + x2.w*wv.w;
        a3 += x3.x*wv.x + x3.y*wv.y + x3.z*wv.z + x3.w*wv.w;
    }
    g_gklat[(m0+rg*4+0)*16 + j] = a0;
    g_gklat[(m0+rg*4+1)*16 + j] = a1;
    g_gklat[(m0+rg*4+2)*16 + j] = a2;
    g_gklat[(m0+rg*4+3)*16 + j] = a3;
}

// ---------------------------------------------------------------------------
// 4) gk stage 2
// ---------------------------------------------------------------------------
__global__ void __launch_bounds__(256) gk2_k(const float* __restrict__ w2,
                                             const float* __restrict__ b2)
{
    __shared__ float lat[64*16];
    int m0 = blockIdx.y * 64;
    int j  = blockIdx.x * 256 + threadIdx.x;
    for (int i = threadIdx.x; i < 64*16; i += 256) lat[i] = g_gklat[m0*16 + i];
    __syncthreads();
    float w[16];
#pragma unroll
    for (int i = 0; i < 16; ++i) w[i] = w2[j*16 + i];
    float bb = b2[j];
    for (int r = 0; r < 64; ++r) {
        float xv = bb;
#pragma unroll
        for (int i = 0; i < 16; ++i) xv += lat[r*16 + i]*w[i];
        float ls = fminf(xv, 0.f) - log1pf(fast_exp(-fabsf(xv)));
        g_gk[(m0+r)*1024 + j] = ls * (1.f/16.f);
    }
}

// ---------------------------------------------------------------------------
// 5) Chunked GLA — tensorized, vc=128 per block, S state in registers.
//    grid (vs 2, bh 32, dir 2) = 128 CTAs (1 wave), 512 threads = 16 warps.
//    Warp (wm4 = w&3, n4 = w>>2):
//      A: rows wm4*16, cols n4*16 ; o: rows wm4*16, cols n4*32
//      U/S: rows (d) wm4*32, cols n4*32 ; S_reg = 32 fp32/thread
//    smem: sg(f32 cumsum) overlaid by A tiles after P2.
// ---------------------------------------------------------------------------
#define OF_SG    0              // 64x132 f32 = 33792  (A_h @ +0, A_l @ +9216 after P2)
#define OF_AH    0
#define OF_AL    9216
#define OF_EBT   33792          // 128 f32
#define OF_QEH   34304          // 64 x 272B
#define OF_QEL   51712
#define OF_KDH   69120
#define OF_KDL   86528
#define OF_VH    103936         // 64 x 272B (vc=128)
#define OF_VL    121344
#define OF_SBH   138752         // 128 x 272B
#define OF_SBL   173568
#define GLA_SMEM_BYTES 208384

__global__ void __launch_bounds__(512, 1) gla_k()
{
    char* sm = s_dyn;
    const uint32_t sb = smem_u32(sm);
    float* sg  = (float*)(sm + OF_SG);
    float* ebt = (float*)(sm + OF_EBT);

    const int vs  = blockIdx.x;      // 0..1 : 128-wide v slice
    const int bh  = blockIdx.y;
    const int dir = blockIdx.z;
    const int b   = bh >> 2;
    const int h   = bh & 3;
    const int tid = threadIdx.x;
    const int lane = tid & 31;
    const int w    = tid >> 5;       // 0..15
    const float scale = 0.088388347648318447f;  // 128^-0.5

    const int qoff = h*HQ;
    const int koff = 512 + h*HQ;
    const int voff = 1024 + h*HV + vs*128;
    const int goff = dir*512 + h*HQ;
    const int rowb = b*NN;
    float* const outp = dir ? g_ob : g_of;

    const int wm4 = w & 3, n4 = w >> 2;
    const int m0w   = wm4*16;   // A/o rows (t)
    const int sA0   = n4*16;    // A cols (s)
    const int vcol0 = n4*32;    // o/U cols (v)
    const int m0u   = wm4*32;   // U rows (d)

    const int aRow = lane & 15;
    const int aSel = ((lane >> 4) & 1) * 16;
    const int bRowL = (lane & 7) + ((lane & 16) ? 8 : 0);
    const int bKof  = (lane & 8) ? 16 : 0;
    const int vRow = (lane & 7) + ((lane >> 3) & 1) * 8;
    const int vSel = ((lane >> 4) & 1) * 16;
    const int tRowT = (lane & 7) + ((lane >> 4) & 1) * 8;
    const int tSelT = ((lane >> 3) & 1) * 16;
    const int g8 = lane >> 2;
    const int q2 = (lane & 3) * 2;

    // master state in registers: warp patch [d: m0u..+32) x [v: vcol0..+32)
    float S_reg[2][4][4];
#pragma unroll
    for (int mt = 0; mt < 2; ++mt)
#pragma unroll
        for (int f = 0; f < 4; ++f)
#pragma unroll
            for (int j = 0; j < 4; ++j) S_reg[mt][f][j] = 0.f;

    for (int c = 0; c < NCH; ++c) {
        // ---- P0: load gk -> sg (f32) ; load+split v -> v_h/v_l ----
#pragma unroll
        for (int it = 0; it < 4; ++it) {
            int j = tid + it*512;
            int t = j >> 5, d4 = (j & 31) * 4;
            int tg = dir ? (NN-1 - (c*64 + t)) : (c*64 + t);
            *(float4*)&sg[t*132 + d4] = *(const float4*)&g_gk[(size_t)(rowb+tg)*1024 + goff + d4];
        }
#pragma unroll
        for (int it = 0; it < 4; ++it) {
            int j = tid + it*512;
            int s = j >> 5, c4 = (j & 31) * 4;
            int tg = dir ? (NN-1 - (c*64 + s)) : (c*64 + s);
            float4 vv = *(const float4*)&g_qkv[(size_t)(rowb+tg)*2048 + voff + c4];
            __nv_bfloat16 h0 = __float2bfloat16(vv.x), h1 = __float2bfloat16(vv.y);
            __nv_bfloat16 h2 = __float2bfloat16(vv.z), h3 = __float2bfloat16(vv.w);
            uint2 hw, lw;
            hw.x = packbf2(vv.x, vv.y); hw.y = packbf2(vv.z, vv.w);
            lw.x = packbf2(vv.x - __bfloat162float(h0), vv.y - __bfloat162float(h1));
            lw.y = packbf2(vv.z - __bfloat162float(h2), vv.w - __bfloat162float(h3));
            *(uint2*)(sm + OF_VH + s*272 + c4*2) = hw;
            *(uint2*)(sm + OF_VL + s*272 + c4*2) = lw;
        }
        __syncthreads();

        // ---- P1: cumsum along t (128 threads) ----
        if (tid < 128) {
            int d = tid;
            float run = 0.f;
#pragma unroll
            for (int blk = 0; blk < 4; ++blk) {
                float r[16];
#pragma unroll
                for (int i = 0; i < 16; ++i) r[i] = sg[(blk*16+i)*132 + d];
#pragma unroll
                for (int i = 0; i < 16; ++i) { run += r[i]; r[i] = run; }
#pragma unroll
                for (int i = 0; i < 16; ++i) sg[(blk*16+i)*132 + d] = r[i];
            }
            ebt[d] = fast_exp(run);
        }
        __syncthreads();

        // ---- P2: qe/kd conversion + write Sb (bf16 hi/lo) from S_reg ----
#pragma unroll
        for (int it = 0; it < 4; ++it) {
            int j = tid + it*512;
            int t = j >> 5, d4 = (j & 31) * 4;
            int tg = dir ? (NN-1 - (c*64 + t)) : (c*64 + t);
            size_t r = (size_t)(rowb+tg)*2048;
            float4 qv = *(const float4*)&g_qkv[r + qoff + d4];
            float4 kv = *(const float4*)&g_qkv[r + koff + d4];
            float4 bv = *(float4*)&sg[t*132 + d4];
            float e0 = fast_exp(bv.x), e1 = fast_exp(bv.y), e2 = fast_exp(bv.z), e3 = fast_exp(bv.w);
            float f0 = fast_exp(-bv.x), f1 = fast_exp(-bv.y), f2 = fast_exp(-bv.z), f3 = fast_exp(-bv.w);
            float q0 = qv.x*e0*scale, q1 = qv.y*e1*scale, q2v = qv.z*e2*scale, q3 = qv.w*e3*scale;
            float k0 = kv.x*f0, k1 = kv.y*f1, k2 = kv.z*f2, k3 = kv.w*f3;
            __nv_bfloat16 qh0 = __float2bfloat16(q0), qh1 = __float2bfloat16(q1);
            __nv_bfloat16 qh2 = __float2bfloat16(q2v), qh3 = __float2bfloat16(q3);
            __nv_bfloat16 kh0 = __float2bfloat16(k0), kh1 = __float2bfloat16(k1);
            __nv_bfloat16 kh2 = __float2bfloat16(k2), kh3 = __float2bfloat16(k3);
            uint2 qhw, qlw, khw, klw;
            qhw.x = packbf2(q0, q1); qhw.y = packbf2(q2v, q3);
            qlw.x = packbf2(q0 - __bfloat162float(qh0), q1 - __bfloat162float(qh1));
            qlw.y = packbf2(q2v - __bfloat162float(qh2), q3 - __bfloat162float(qh3));
            khw.x = packbf2(k0, k1); khw.y = packbf2(k2, k3);
            klw.x = packbf2(k0 - __bfloat162float(kh0), k1 - __bfloat162float(kh1));
            klw.y = packbf2(k2 - __bfloat162float(kh2), k3 - __bfloat162float(kh3));
            *(uint2*)(sm + OF_QEH + t*272 + d4*2) = qhw;
            *(uint2*)(sm + OF_QEL + t*272 + d4*2) = qlw;
            *(uint2*)(sm + OF_KDH + t*272 + d4*2) = khw;
            *(uint2*)(sm + OF_KDL + t*272 + d4*2) = klw;
        }
        // Sb from registers (each warp writes its own patch)
#pragma unroll
        for (int mt = 0; mt < 2; ++mt)
#pragma unroll
            for (int f = 0; f < 4; ++f)
#pragma unroll
                for (int hh = 0; hh < 2; ++hh) {
                    int d  = m0u + mt*16 + hh*8 + g8;
                    int vc = vcol0 + f*8 + q2;
                    float v0 = S_reg[mt][f][hh*2+0];
                    float v1 = S_reg[mt][f][hh*2+1];
                    __nv_bfloat16 s0 = __float2bfloat16(v0), s1 = __float2bfloat16(v1);
                    *(uint32_t*)(sm + OF_SBH + d*272 + vc*2) = packbf2(v0, v1);
                    *(uint32_t*)(sm + OF_SBL + d*272 + vc*2) =
                        packbf2(v0 - __bfloat162float(s0), v1 - __bfloat162float(s1));
                }
        __syncthreads();

        // ---- P3: A = qe @ kd^T (64x64, k=128), mask, -> A_h/A_l (sg overlay) ----
        {
            float acc[2][4];
#pragma unroll
            for (int f = 0; f < 2; ++f)
#pragma unroll
                for (int j = 0; j < 4; ++j) acc[f][j] = 0.f;
#pragma unroll
            for (int ks = 0; ks < 8; ++ks) {
                int kb = ks * 32;
                uint32_t aH[4], aL[4];
                ldsm4(aH, sb + OF_QEH + (m0w + aRow)*272 + kb + aSel);
                ldsm4(aL, sb + OF_QEL + (m0w + aRow)*272 + kb + aSel);
                uint32_t bh[4], bl[4];
                ldsm4(bh, sb + OF_KDH + (sA0 + bRowL)*272 + kb + bKof);
                ldsm4(bl, sb + OF_KDL + (sA0 + bRowL)*272 + kb + bKof);
                mma16816(acc[0], aH, bh[0], bh[1]);
                mma16816(acc[1], aH, bh[2], bh[3]);
                mma16816(acc[0], aH, bl[0], bl[1]);
                mma16816(acc[1], aH, bl[2], bl[3]);
                mma16816(acc[0], aL, bh[0], bh[1]);
                mma16816(acc[1], aL, bh[2], bh[3]);
            }
            __syncthreads();   // sg reads (P2) done; safe to overlay A into sg region
#pragma unroll
            for (int f = 0; f < 2; ++f) {
                int scol = sA0 + f*8 + q2;
#pragma unroll
                for (int hh = 0; hh < 2; ++hh) {
                    int t = m0w + g8 + hh*8;
                    float v0 = (scol     <= t) ? acc[f][hh*2+0] : 0.f;
                    float v1 = (scol + 1 <= t) ? acc[f][hh*2+1] : 0.f;
                    __nv_bfloat16 a0 = __float2bfloat16(v0), a1 = __float2bfloat16(v1);
                    *(uint32_t*)(sm + OF_AH + t*144 + scol*2) = packbf2(v0, v1);
                    *(uint32_t*)(sm + OF_AL + t*144 + scol*2) =
                        packbf2(v0 - __bfloat162float(a0), v1 - __bfloat162float(a1));
                }
            }
        }
        __syncthreads();

        // ---- P4: o = qe@Sb + A@v -> gmem ; U = kd^T@v accumulated into S_reg ----
        {
            float acc[4][4];
#pragma unroll
            for (int f = 0; f < 4; ++f)
#pragma unroll
                for (int j = 0; j < 4; ++j) acc[f][j] = 0.f;
            // qe @ Sb  (k = d = 128)
#pragma unroll
            for (int ks = 0; ks < 8; ++ks) {
                int kb = ks * 32;
                uint32_t aH[4], aL[4];
                ldsm4(aH, sb + OF_QEH + (m0w + aRow)*272 + kb + aSel);
                ldsm4(aL, sb + OF_QEL + (m0w + aRow)*272 + kb + aSel);
                uint32_t b0h[4], b1h[4], b0l[4], b1l[4];
                uint32_t sr = (ks*16 + vRow)*272;
                ldsm4t(b0h, sb + OF_SBH + sr + vcol0*2 + vSel);
                ldsm4t(b1h, sb + OF_SBH + sr + (vcol0 + 16)*2 + vSel);
                ldsm4t(b0l, sb + OF_SBL + sr + vcol0*2 + vSel);
                ldsm4t(b1l, sb + OF_SBL + sr + (vcol0 + 16)*2 + vSel);
                mma16816(acc[0], aH, b0h[0], b0h[1]);
                mma16816(acc[1], aH, b0h[2], b0h[3]);
                mma16816(acc[2], aH, b1h[0], b1h[1]);
                mma16816(acc[3], aH, b1h[2], b1h[3]);
                mma16816(acc[0], aH, b0l[0], b0l[1]);
                mma16816(acc[1], aH, b0l[2], b0l[3]);
                mma16816(acc[2], aH, b1l[0], b1l[1]);
                mma16816(acc[3], aH, b1l[2], b1l[3]);
                mma16816(acc[0], aL, b0h[0], b0h[1]);
                mma16816(acc[1], aL, b0h[2], b0h[3]);
                mma16816(acc[2], aL, b1h[0], b1h[1]);
                mma16816(acc[3], aL, b1h[2], b1h[3]);
            }
            // A@v (into acc) and kd^T@v (into S_reg), sharing v fragments. k = t = 64
#pragma unroll
            for (int ks = 0; ks < 4; ++ks) {
                int kb = ks * 32;
                uint32_t b0h[4], b1h[4], b0l[4], b1l[4];
                uint32_t vr = (ks*16 + vRow)*272;
                ldsm4t(b0h, sb + OF_VH + vr + vcol0*2 + vSel);
                ldsm4t(b1h, sb + OF_VH + vr + (vcol0 + 16)*2 + vSel);
                ldsm4t(b0l, sb + OF_VL + vr + vcol0*2 + vSel);
                ldsm4t(b1l, sb + OF_VL + vr + (vcol0 + 16)*2 + vSel);
                // A @ v
                {
                    uint32_t aH[4], aL[4];
                    ldsm4(aH, sb + OF_AH + (m0w + aRow)*144 + kb + aSel);
                    ldsm4(aL, sb + OF_AL + (m0w + aRow)*144 + kb + aSel);
                    mma16816(acc[0], aH, b0h[0], b0h[1]);
                    mma16816(acc[1], aH, b0h[2], b0h[3]);
                    mma16816(acc[2], aH, b1h[0], b1h[1]);
                    mma16816(acc[3], aH, b1h[2], b1h[3]);
                    mma16816(acc[0], aH, b0l[0], b0l[1]);
                    mma16816(acc[1], aH, b0l[2], b0l[3]);
                    mma16816(acc[2], aH, b1l[0], b1l[1]);
                    mma16816(acc[3], aH, b1l[2], b1l[3]);
                    mma16816(acc[0], aL, b0h[0], b0h[1]);
                    mma16816(acc[1], aL, b0h[2], b0h[3]);
                    mma16816(acc[2], aL, b1h[0], b1h[1]);
                    mma16816(acc[3], aL, b1h[2], b1h[3]);
                }
                // kd^T @ v  -> S_reg
                uint32_t tr = (ks*16 + tRowT)*272;
#pragma unroll
                for (int mt = 0; mt < 2; ++mt) {
                    uint32_t dby = (m0u + mt*16)*2 + tSelT;
                    uint32_t aTh[4], aTl[4];
                    ldsm4t(aTh, sb + OF_KDH + tr + dby);
                    ldsm4t(aTl, sb + OF_KDL + tr + dby);
                    mma16816(S_reg[mt][0], aTh, b0h[0], b0h[1]);
                    mma16816(S_reg[mt][1], aTh, b0h[2], b0h[3]);
                    mma16816(S_reg[mt][2], aTh, b1h[0], b1h[1]);
                    mma16816(S_reg[mt][3], aTh, b1h[2], b1h[3]);
                    mma16816(S_reg[mt][0], aTh, b0l[0], b0l[1]);
                    mma16816(S_reg[mt][1], aTh, b0l[2], b0l[3]);
                    mma16816(S_reg[mt][2], aTh, b1l[0], b1l[1]);
                    mma16816(S_reg[mt][3], aTh, b1l[2], b1l[3]);
                    mma16816(S_reg[mt][0], aTl, b0h[0], b0h[1]);
                    mma16816(S_reg[mt][1], aTl, b0h[2], b0h[3]);
                    mma16816(S_reg[mt][2], aTl, b1h[0], b1h[1]);
                    mma16816(S_reg[mt][3], aTl, b1h[2], b1h[3]);
                }
            }
            // write o
#pragma unroll
            for (int f = 0; f < 4; ++f) {
                int col = vcol0 + f*8 + q2;
#pragma unroll
                for (int hh = 0; hh < 2; ++hh) {
                    int t = m0w + g8 + hh*8;
                    int tg = dir ? (NN-1 - (c*64 + t)) : (c*64 + t);
                    float2 vv; vv.x = acc[f][hh*2+0]; vv.y = acc[f][hh*2+1];
                    *(float2*)&outp[(size_t)(bh*NN + tg)*256 + vs*128 + col] = vv;
                }
            }
            // S = exp(btot) * S   (U already accumulated)
#pragma unroll
            for (int mt = 0; mt < 2; ++mt)
#pragma unroll
                for (int hh = 0; hh < 2; ++hh) {
                    float e = ebt[m0u + mt*16 + hh*8 + g8];
#pragma unroll
                    for (int f = 0; f < 4; ++f) {
                        S_reg[mt][f][hh*2+0] *= e;
                        S_reg[mt][f][hh*2+1] *= e;
                    }
                }
        }
        __syncthreads();
    }
}

// ---------------------------------------------------------------------------
// 6) combine -> fp16 hi/lo for the output GEMM
// ---------------------------------------------------------------------------
__global__ void __launch_bounds__(256) combine_k(const float* __restrict__ gnw,
                                                 const float* __restrict__ lnw)
{
    __shared__ float red[16];
    int idx = blockIdx.x;
    int bh  = idx / NN, t = idx % NN;
    int b   = bh >> 2,  h = bh & 3;
    int v   = threadIdx.x;
    float of = g_of[(size_t)idx*256 + v];
    float ob = g_ob[(size_t)idx*256 + v];
    float sf = of*of, sb = ob*ob;
#pragma unroll
    for (int o = 16; o > 0; o >>= 1) {
        sf += __shfl_xor_sync(0xffffffffu, sf, o);
        sb += __shfl_xor_sync(0xffffffffu, sb, o);
    }
    int w = v >> 5, l = v & 31;
    if (l == 0) { red[w] = sf; red[8+w] = sb; }
    __syncthreads();
    float tf = 0.f, tb = 0.f;
#pragma unroll
    for (int i = 0; i < 8; ++i) { tf += red[i]; tb += red[8+i]; }
    float inf_ = rsqrtf(tf*(1.f/256.f) + 1e-5f);
    float inb_ = rsqrtf(tb*(1.f/256.f) + 1e-5f);
    float o = of*inf_*gnw[v] + ob*inb_*lnw[v];
    int gi = (b*NN + t)*1024 + h*256 + v;
    float val = o * g_g[gi];
    __half hh = __float2half(val);
    g_oc_h[gi] = hh;
    g_oc_l[gi] = __float2half(val - __half2float(hh));
}

// ---------------------------------------------------------------------------
// launcher
// ---------------------------------------------------------------------------
extern "C" void kernel_launch(void* const* d_in, const int* in_sizes, int n_in,
                              void* d_out, int out_size)
{
    const float* x     = (const float*)d_in[0];
    const float* convw = (const float*)d_in[1];
    const float* qkvw  = (const float*)d_in[2];
    const float* gkw1  = (const float*)d_in[3];
    const float* gkw2  = (const float*)d_in[4];
    const float* gkb2  = (const float*)d_in[5];
    const float* gw    = (const float*)d_in[6];
    const float* gb    = (const float*)d_in[7];
    const float* gnw   = (const float*)d_in[8];
    const float* lnw   = (const float*)d_in[9];
    const float* ow    = (const float*)d_in[10];
    float* out = (float*)d_out;

    cudaFuncSetAttribute(gla_k, cudaFuncAttributeMaxDynamicSharedMemorySize, GLA_SMEM_BYTES);
    cudaFuncSetAttribute(gemm128_k<0>, cudaFuncAttributeMaxDynamicSharedMemorySize, GEMM_SMEM);
    cudaFuncSetAttribute(gemm128_k<1>, cudaFuncAttributeMaxDynamicSharedMemorySize, GEMM_SMEM);

    float *p_qkv, *p_g;
    __half *p_xs_h, *p_xs_l, *p_oc_h, *p_oc_l;
    __half *p_wq_h, *p_wg_h, *p_wo_h;
    cudaGetSymbolAddress((void**)&p_qkv,  g_qkv);
    cudaGetSymbolAddress((void**)&p_g,    g_g);
    cudaGetSymbolAddress((void**)&p_xs_h, g_xs_h);
    cudaGetSymbolAddress((void**)&p_xs_l, g_xs_l);
    cudaGetSymbolAddress((void**)&p_oc_h, g_oc_h);
    cudaGetSymbolAddress((void**)&p_oc_l, g_oc_l);
    cudaGetSymbolAddress((void**)&p_wq_h, g_wq_h);
    cudaGetSymbolAddress((void**)&p_wg_h, g_wg_h);
    cudaGetSymbolAddress((void**)&p_wo_h, g_wo_h);

    cvt_h_k<<<(2048*512 + 255)/256, 256>>>(qkvw, p_wq_h, 2048*512);
    cvt_h_k<<<(1024*512 + 255)/256, 256>>>(gw,   p_wg_h, 1024*512);
    cvt_h_k<<<(512*1024 + 255)/256, 256>>>(ow,   p_wo_h, 512*1024);

    conv_silu_k<<<MROWS, 512>>>(x, convw);

    gemm128_k<0><<<dim3(2048/128, MROWS/128), 256, GEMM_SMEM>>>(p_xs_h, p_xs_l, p_wq_h, nullptr, p_qkv, 2048, 512);
    gemm128_k<1><<<dim3(1024/128, MROWS/128), 256, GEMM_SMEM>>>(p_xs_h, p_xs_l, p_wg_h, gb, p_g, 1024, 512);

    gk1_k<<<MROWS/64, 256>>>(gkw1);
    gk2_k<<<dim3(4, MROWS/64), 256>>>(gkw2, gkb2);
    gla_k<<<dim3(2, BB*NH, 2), 512, GLA_SMEM_BYTES>>>();
    combine_k<<<BB*NH*NN, 256>>>(gnw, lnw);

    gemm128_k<0><<<dim3(512/128, MROWS/128), 256, GEMM_SMEM>>>(p_oc_h, p_oc_l, p_wo_h, nullptr, out, 512, 1024);
}

// round 17
// speedup vs baseline: 1.5441x; 1.0685x over previous
#include <cuda_runtime.h>
#include <cuda_bf16.h>
#include <cuda_fp16.h>
#include <math.h>
#include <stdint.h>

// ---------------------------------------------------------------------------
// Problem constants
// ---------------------------------------------------------------------------
#define BB     8
#define NN     3136
#define HH_    56
#define WW_    56
#define DM     512
#define NH     4
#define HQ     128
#define HV     256
#define CH     64
#define NCH    49
#define MROWS  (BB*NN)       // 25088

// ---------------------------------------------------------------------------
// Scratch
// ---------------------------------------------------------------------------
static __device__ float g_xs   [MROWS*DM];
static __device__ __half g_xs_h[MROWS*DM];
static __device__ __half g_xs_l[MROWS*DM];
static __device__ float g_qkv  [MROWS*2048];
static __device__ float g_g    [MROWS*1024];
static __device__ float g_gklat[MROWS*16];
static __device__ float g_gk   [MROWS*1024];
static __device__ float g_of   [MROWS*1024];
static __device__ float g_ob   [MROWS*1024];
static __device__ __half g_oc_h[MROWS*1024];
static __device__ __half g_oc_l[MROWS*1024];
static __device__ __half g_wqg_h[3072*512];    // fused qkv (0..2047) + gate (2048..3071) weights
static __device__ __half g_wo_h[512*1024];

// ---------------------------------------------------------------------------
// fast exp on the FMA/ALU pipes (no MUFU)
// ---------------------------------------------------------------------------
__device__ __forceinline__ float fast_exp(float x) {
    float t = x * 1.4426950408889634f;
    float z = t + 12582912.0f;            // 1.5 * 2^23
    int   n = __float_as_int(z);
    float fr = t - (z - 12582912.0f);
    float p = 0.00015403530393381608f;
    p = fmaf(p, fr, 0.0013333558146428443f);
    p = fmaf(p, fr, 0.009618129107628477f);
    p = fmaf(p, fr, 0.05550410866482158f);
    p = fmaf(p, fr, 0.2402265069591007f);
    p = fmaf(p, fr, 0.6931471805599453f);
    p = fmaf(p, fr, 1.0f);
    return __int_as_float(__float_as_int(p) + (n << 23));
}
__device__ __forceinline__ float sigm(float x) {
    return __fdividef(1.f, 1.f + fast_exp(-x));
}

__device__ __forceinline__ uint32_t smem_u32(const void* p) {
    uint32_t a;
    asm("{ .reg .u64 t; cvta.to.shared.u64 t, %1; cvt.u32.u64 %0, t; }" : "=r"(a) : "l"(p));
    return a;
}
__device__ __forceinline__ void cp16(uint32_t dst, const void* src) {
    asm volatile("cp.async.cg.shared.global [%0], [%1], 16;" :: "r"(dst), "l"(src));
}
#define CP_COMMIT() asm volatile("cp.async.commit_group;" ::: "memory")
#define CP_WAIT0()  asm volatile("cp.async.wait_group 0;" ::: "memory")
#define CP_WAIT1()  asm volatile("cp.async.wait_group 1;" ::: "memory")

__device__ __forceinline__ void ldsm4(uint32_t* r, uint32_t addr) {
    asm volatile("ldmatrix.sync.aligned.m8n8.x4.shared.b16 {%0,%1,%2,%3}, [%4];"
        : "=r"(r[0]), "=r"(r[1]), "=r"(r[2]), "=r"(r[3]) : "r"(addr));
}
__device__ __forceinline__ void ldsm4t(uint32_t* r, uint32_t addr) {
    asm volatile("ldmatrix.sync.aligned.m8n8.x4.trans.shared.b16 {%0,%1,%2,%3}, [%4];"
        : "=r"(r[0]), "=r"(r[1]), "=r"(r[2]), "=r"(r[3]) : "r"(addr));
}
// bf16 mma (GLA)
__device__ __forceinline__ void mma16816(float* c, const uint32_t* a, uint32_t b0, uint32_t b1) {
    asm volatile("mma.sync.aligned.m16n8k16.row.col.f32.bf16.bf16.f32 "
        "{%0,%1,%2,%3}, {%4,%5,%6,%7}, {%8,%9}, {%0,%1,%2,%3};"
        : "+f"(c[0]), "+f"(c[1]), "+f"(c[2]), "+f"(c[3])
        : "r"(a[0]), "r"(a[1]), "r"(a[2]), "r"(a[3]), "r"(b0), "r"(b1));
}
// fp16 mma (GEMMs)
__device__ __forceinline__ void mma16816h(float* c, const uint32_t* a, uint32_t b0, uint32_t b1) {
    asm volatile("mma.sync.aligned.m16n8k16.row.col.f32.f16.f16.f32 "
        "{%0,%1,%2,%3}, {%4,%5,%6,%7}, {%8,%9}, {%0,%1,%2,%3};"
        : "+f"(c[0]), "+f"(c[1]), "+f"(c[2]), "+f"(c[3])
        : "r"(a[0]), "r"(a[1]), "r"(a[2]), "r"(a[3]), "r"(b0), "r"(b1));
}

__device__ __forceinline__ uint32_t packbf2(float a, float b) {
    __nv_bfloat162 t;
    t.x = __float2bfloat16(a);
    t.y = __float2bfloat16(b);
    return *(uint32_t*)&t;
}

extern __shared__ char s_dyn[];

// ---------------------------------------------------------------------------
// 1) depthwise 3x3 conv + SiLU, emit fp32 + fp16 hi/lo
// ---------------------------------------------------------------------------
__global__ void __launch_bounds__(512) conv_silu_k(const float* __restrict__ x,
                                                   const float* __restrict__ w)
{
    int bn = blockIdx.x;
    int b  = bn / NN, n = bn % NN;
    int y  = n / WW_, xx = n % WW_;
    int c  = threadIdx.x;
    float wr[9];
#pragma unroll
    for (int i = 0; i < 9; ++i) wr[i] = w[c*9 + i];
    float acc = 0.f;
#pragma unroll
    for (int ky = 0; ky < 3; ++ky) {
        int yy = y + ky - 1;
        if (yy < 0 || yy >= HH_) continue;
#pragma unroll
        for (int kx = 0; kx < 3; ++kx) {
            int xc = xx + kx - 1;
            if (xc < 0 || xc >= WW_) continue;
            acc += x[(b*NN + yy*WW_ + xc)*DM + c] * wr[ky*3 + kx];
        }
    }
    float r = acc * sigm(acc);
    g_xs[bn*DM + c] = r;
    __half h = __float2half(r);
    g_xs_h[bn*DM + c] = h;
    g_xs_l[bn*DM + c] = __float2half(r - __half2float(h));
}

// ---------------------------------------------------------------------------
// fp16 conversion for weights
// ---------------------------------------------------------------------------
__global__ void __launch_bounds__(256) cvt_h_k(const float* __restrict__ s,
                                               __half* __restrict__ h, int n)
{
    int i = blockIdx.x*256 + threadIdx.x;
    if (i < n) h[i] = __float2half(s[i]);
}

// ---------------------------------------------------------------------------
// 2) fp16x2 GEMM (NT): C = (Ah+Al) . Bh^T ; fp32 accum, mma.sync m16n8k16
//    EPI 0: plain C (Nc stride). EPI 2: fused qkv/gate routing:
//      n<2048 -> C[row*2048+n] ; n>=2048 -> silu(v+bias[n-2048]) -> C2[row*1024+..]
// ---------------------------------------------------------------------------
#define GEMM_STAGE 49152
#define GEMM_SMEM  (2*GEMM_STAGE)

template<int EPI>
__global__ void __launch_bounds__(256, 2)
gemm128_k(const __half* __restrict__ Ah, const __half* __restrict__ Al,
          const __half* __restrict__ Bh,
          const float* __restrict__ bias, float* __restrict__ C,
          float* __restrict__ C2, int Nc, int K)
{
    const int tid  = threadIdx.x;
    const int lane = tid & 31;
    const int wid  = tid >> 5;
    const int wm   = (wid & 3) * 32;
    const int wn   = (wid >> 2) * 64;
    const int n0 = blockIdx.x * 128, m0 = blockIdx.y * 128;
    const uint32_t sb = smem_u32(s_dyn);
    const int nk = K >> 6;

    float acc[2][8][4];
#pragma unroll
    for (int i = 0; i < 2; ++i)
#pragma unroll
        for (int j = 0; j < 8; ++j)
#pragma unroll
            for (int q = 0; q < 4; ++q) acc[i][j][q] = 0.f;

    auto load_chunk = [&](int kc) {
        uint32_t tb = sb + (kc & 1) * GEMM_STAGE;
        int kb = kc << 6;
#pragma unroll
        for (int it = 0; it < 4; ++it) {
            int i = tid + it*256;
            int row = i >> 3, seg = i & 7;
            uint32_t off = (uint32_t)(row*128 + seg*16);
            uint32_t sw = off ^ ((off >> 3) & 0x70);
            const __half* pAh = Ah + (size_t)(m0 + row)*K + kb + seg*8;
            const __half* pAl = Al + (size_t)(m0 + row)*K + kb + seg*8;
            const __half* pBh = Bh + (size_t)(n0 + row)*K + kb + seg*8;
            cp16(tb +         sw, pAh);
            cp16(tb + 16384 + sw, pAl);
            cp16(tb + 32768 + sw, pBh);
        }
    };

    load_chunk(0); CP_COMMIT();

    const int aRow = lane & 15;
    const int aKof = ((lane >> 4) & 1) * 16;
    const int bRowL = (lane & 7) + ((lane & 16) ? 8 : 0);
    const int bKof = (lane & 8) ? 16 : 0;

    for (int c = 0; c < nk; ++c) {
        if (c + 1 < nk) { load_chunk(c + 1); CP_COMMIT(); CP_WAIT1(); }
        else            { CP_WAIT0(); }
        __syncthreads();

        uint32_t tb = sb + (c & 1) * GEMM_STAGE;
#pragma unroll
        for (int ks = 0; ks < 4; ++ks) {
            const int kbyte = ks * 32;
            uint32_t aH[2][4], aL[2][4];
#pragma unroll
            for (int mt = 0; mt < 2; ++mt) {
                uint32_t off = (uint32_t)((wm + mt*16 + aRow) * 128 + kbyte + aKof);
                uint32_t sw = off ^ ((off >> 3) & 0x70);
                ldsm4(aH[mt], tb + sw);
                ldsm4(aL[mt], tb + 16384 + sw);
            }
#pragma unroll
            for (int ntp = 0; ntp < 4; ++ntp) {
                uint32_t off = (uint32_t)((wn + ntp*16 + bRowL) * 128 + kbyte + bKof);
                uint32_t sw = off ^ ((off >> 3) & 0x70);
                uint32_t bh[4];
                ldsm4(bh, tb + 32768 + sw);
#pragma unroll
                for (int mt = 0; mt < 2; ++mt) {
                    mma16816h(acc[mt][ntp*2+0], aH[mt], bh[0], bh[1]);
                    mma16816h(acc[mt][ntp*2+1], aH[mt], bh[2], bh[3]);
                    mma16816h(acc[mt][ntp*2+0], aL[mt], bh[0], bh[1]);
                    mma16816h(acc[mt][ntp*2+1], aL[mt], bh[2], bh[3]);
                }
            }
        }
        __syncthreads();
    }

    const int rbase = m0 + wm + (lane >> 2);
    const int cbase = n0 + wn + (lane & 3) * 2;
#pragma unroll
    for (int mt = 0; mt < 2; ++mt) {
#pragma unroll
        for (int nt = 0; nt < 8; ++nt) {
            int col = cbase + nt*8;
#pragma unroll
            for (int half = 0; half < 2; ++half) {
                int row = rbase + mt*16 + half*8;
                float v0 = acc[mt][nt][half*2+0];
                float v1 = acc[mt][nt][half*2+1];
                if (EPI == 2) {
                    if (col < 2048) {
                        float2 vv; vv.x = v0; vv.y = v1;
                        *(float2*)&C[(size_t)row*2048 + col] = vv;
                    } else {
                        int c2 = col - 2048;
                        v0 += bias[c2+0]; v0 *= sigm(v0);
                        v1 += bias[c2+1]; v1 *= sigm(v1);
                        float2 vv; vv.x = v0; vv.y = v1;
                        *(float2*)&C2[(size_t)row*1024 + c2] = vv;
                    }
                } else {
                    float2 vv; vv.x = v0; vv.y = v1;
                    *(float2*)&C[(size_t)row*Nc + col] = vv;
                }
            }
        }
    }
}

// ---------------------------------------------------------------------------
// 3) gk low-rank stage 1
// ---------------------------------------------------------------------------
__global__ void __launch_bounds__(256) gk1_k(const float* __restrict__ w1)
{
    __shared__ float w1s[16*DM];
    int tid = threadIdx.x;
    for (int i = tid; i < 16*DM; i += 256) w1s[i] = w1[i];
    __syncthreads();
    int m0 = blockIdx.x * 64;
    int j  = tid & 15, rg = tid >> 4;
    const float* xb = &g_xs[(m0 + rg*4)*DM];
    const float4* w4 = (const float4*)&w1s[j*DM];
    float a0 = 0.f, a1 = 0.f, a2 = 0.f, a3 = 0.f;
#pragma unroll 4
    for (int k = 0; k < DM/4; ++k) {
        float4 wv = w4[k];
        float4 x0 = *(const float4*)&xb[0*DM + k*4];
        float4 x1 = *(const float4*)&xb[1*DM + k*4];
        float4 x2 = *(const float4*)&xb[2*DM + k*4];
        float4 x3 = *(const float4*)&xb[3*DM + k*4];
        a0 += x0.x*wv.x + x0.y*wv.y + x0.z*wv.z + x0.w*wv.w;
        a1 += x1.x*wv.x + x1.y*wv.y + x1.z*wv.z + x1.w*wv.w;
        a2 += x2.x*wv.x + x2.y*wv.y + x2.z*wv.z + x2.w*wv.w;
        a3 += x3.x*wv.x + x3.y*wv.y + x3.z*wv.z + x3.w*wv.w;
    }
    g_gklat[(m0+rg*4+0)*16 + j] = a0;
    g_gklat[(m0+rg*4+1)*16 + j] = a1;
    g_gklat[(m0+rg*4+2)*16 + j] = a2;
    g_gklat[(m0+rg*4+3)*16 + j] = a3;
}

// ---------------------------------------------------------------------------
// 4) gk stage 2
// ---------------------------------------------------------------------------
__global__ void __launch_bounds__(256) gk2_k(const float* __restrict__ w2,
                                             const float* __restrict__ b2)
{
    __shared__ float lat[64*16];
    int m0 = blockIdx.y * 64;
    int j  = blockIdx.x * 256 + threadIdx.x;
    for (int i = threadIdx.x; i < 64*16; i += 256) lat[i] = g_gklat[m0*16 + i];
    __syncthreads();
    float w[16];
#pragma unroll
    for (int i = 0; i < 16; ++i) w[i] = w2[j*16 + i];
    float bb = b2[j];
    for (int r = 0; r < 64; ++r) {
        float xv = bb;
#pragma unroll
        for (int i = 0; i < 16; ++i) xv += lat[r*16 + i]*w[i];
        float ls = fminf(xv, 0.f) - log1pf(fast_exp(-fabsf(xv)));
        g_gk[(m0+r)*1024 + j] = ls * (1.f/16.f);
    }
}

// ---------------------------------------------------------------------------
// 5) Chunked GLA — tensorized, vc=128 per block, S state in registers.
//    grid (vs 2, bh 32, dir 2) = 128 CTAs (1 wave), 512 threads = 16 warps.
//    Causal-mask skips: P3 zero-blocks skipped; P4 A@v k-range = triangle.
// ---------------------------------------------------------------------------
#define OF_SG    0              // 64x132 f32 (A_h @ +0, A_l @ +9216 after P2)
#define OF_AH    0
#define OF_AL    9216
#define OF_EBT   33792          // 128 f32
#define OF_QEH   34304          // 64 x 272B
#define OF_QEL   51712
#define OF_KDH   69120
#define OF_KDL   86528
#define OF_VH    103936         // 64 x 272B (vc=128)
#define OF_VL    121344
#define OF_SBH   138752         // 128 x 272B
#define OF_SBL   173568
#define GLA_SMEM_BYTES 208384

__global__ void __launch_bounds__(512, 1) gla_k()
{
    char* sm = s_dyn;
    const uint32_t sb = smem_u32(sm);
    float* sg  = (float*)(sm + OF_SG);
    float* ebt = (float*)(sm + OF_EBT);

    const int vs  = blockIdx.x;
    const int bh  = blockIdx.y;
    const int dir = blockIdx.z;
    const int b   = bh >> 2;
    const int h   = bh & 3;
    const int tid = threadIdx.x;
    const int lane = tid & 31;
    const int w    = tid >> 5;
    const float scale = 0.088388347648318447f;  // 128^-0.5

    const int qoff = h*HQ;
    const int koff = 512 + h*HQ;
    const int voff = 1024 + h*HV + vs*128;
    const int goff = dir*512 + h*HQ;
    const int rowb = b*NN;
    float* const outp = dir ? g_ob : g_of;

    const int wm4 = w & 3, n4 = w >> 2;
    const int m0w   = wm4*16;
    const int sA0   = n4*16;
    const int vcol0 = n4*32;
    const int m0u   = wm4*32;

    const int aRow = lane & 15;
    const int aSel = ((lane >> 4) & 1) * 16;
    const int bRowL = (lane & 7) + ((lane & 16) ? 8 : 0);
    const int bKof  = (lane & 8) ? 16 : 0;
    const int vRow = (lane & 7) + ((lane >> 3) & 1) * 8;
    const int vSel = ((lane >> 4) & 1) * 16;
    const int tRowT = (lane & 7) + ((lane >> 4) & 1) * 8;
    const int tSelT = ((lane >> 3) & 1) * 16;
    const int g8 = lane >> 2;
    const int q2 = (lane & 3) * 2;

    float S_reg[2][4][4];
#pragma unroll
    for (int mt = 0; mt < 2; ++mt)
#pragma unroll
        for (int f = 0; f < 4; ++f)
#pragma unroll
            for (int j = 0; j < 4; ++j) S_reg[mt][f][j] = 0.f;

    for (int c = 0; c < NCH; ++c) {
        // ---- P0: load gk -> sg ; load+split v ----
#pragma unroll
        for (int it = 0; it < 4; ++it) {
            int j = tid + it*512;
            int t = j >> 5, d4 = (j & 31) * 4;
            int tg = dir ? (NN-1 - (c*64 + t)) : (c*64 + t);
            *(float4*)&sg[t*132 + d4] = *(const float4*)&g_gk[(size_t)(rowb+tg)*1024 + goff + d4];
        }
#pragma unroll
        for (int it = 0; it < 4; ++it) {
            int j = tid + it*512;
            int s = j >> 5, c4 = (j & 31) * 4;
            int tg = dir ? (NN-1 - (c*64 + s)) : (c*64 + s);
            float4 vv = *(const float4*)&g_qkv[(size_t)(rowb+tg)*2048 + voff + c4];
            __nv_bfloat16 h0 = __float2bfloat16(vv.x), h1 = __float2bfloat16(vv.y);
            __nv_bfloat16 h2 = __float2bfloat16(vv.z), h3 = __float2bfloat16(vv.w);
            uint2 hw, lw;
            hw.x = packbf2(vv.x, vv.y); hw.y = packbf2(vv.z, vv.w);
            lw.x = packbf2(vv.x - __bfloat162float(h0), vv.y - __bfloat162float(h1));
            lw.y = packbf2(vv.z - __bfloat162float(h2), vv.w - __bfloat162float(h3));
            *(uint2*)(sm + OF_VH + s*272 + c4*2) = hw;
            *(uint2*)(sm + OF_VL + s*272 + c4*2) = lw;
        }
        __syncthreads();

        // ---- P1: cumsum ----
        if (tid < 128) {
            int d = tid;
            float run = 0.f;
#pragma unroll
            for (int blk = 0; blk < 4; ++blk) {
                float r[16];
#pragma unroll
                for (int i = 0; i < 16; ++i) r[i] = sg[(blk*16+i)*132 + d];
#pragma unroll
                for (int i = 0; i < 16; ++i) { run += r[i]; r[i] = run; }
#pragma unroll
                for (int i = 0; i < 16; ++i) sg[(blk*16+i)*132 + d] = r[i];
            }
            ebt[d] = fast_exp(run);
        }
        __syncthreads();

        // ---- P2: qe/kd conversion + Sb from S_reg ----
#pragma unroll
        for (int it = 0; it < 4; ++it) {
            int j = tid + it*512;
            int t = j >> 5, d4 = (j & 31) * 4;
            int tg = dir ? (NN-1 - (c*64 + t)) : (c*64 + t);
            size_t r = (size_t)(rowb+tg)*2048;
            float4 qv = *(const float4*)&g_qkv[r + qoff + d4];
            float4 kv = *(const float4*)&g_qkv[r + koff + d4];
            float4 bv = *(float4*)&sg[t*132 + d4];
            float e0 = fast_exp(bv.x), e1 = fast_exp(bv.y), e2 = fast_exp(bv.z), e3 = fast_exp(bv.w);
            float f0 = fast_exp(-bv.x), f1 = fast_exp(-bv.y), f2 = fast_exp(-bv.z), f3 = fast_exp(-bv.w);
            float q0 = qv.x*e0*scale, q1 = qv.y*e1*scale, q2v = qv.z*e2*scale, q3 = qv.w*e3*scale;
            float k0 = kv.x*f0, k1 = kv.y*f1, k2 = kv.z*f2, k3 = kv.w*f3;
            __nv_bfloat16 qh0 = __float2bfloat16(q0), qh1 = __float2bfloat16(q1);
            __nv_bfloat16 qh2 = __float2bfloat16(q2v), qh3 = __float2bfloat16(q3);
            __nv_bfloat16 kh0 = __float2bfloat16(k0), kh1 = __float2bfloat16(k1);
            __nv_bfloat16 kh2 = __float2bfloat16(k2), kh3 = __float2bfloat16(k3);
            uint2 qhw, qlw, khw, klw;
            qhw.x = packbf2(q0, q1); qhw.y = packbf2(q2v, q3);
            qlw.x = packbf2(q0 - __bfloat162float(qh0), q1 - __bfloat162float(qh1));
            qlw.y = packbf2(q2v - __bfloat162float(qh2), q3 - __bfloat162float(qh3));
            khw.x = packbf2(k0, k1); khw.y = packbf2(k2, k3);
            klw.x = packbf2(k0 - __bfloat162float(kh0), k1 - __bfloat162float(kh1));
            klw.y = packbf2(k2 - __bfloat162float(kh2), k3 - __bfloat162float(kh3));
            *(uint2*)(sm + OF_QEH + t*272 + d4*2) = qhw;
            *(uint2*)(sm + OF_QEL + t*272 + d4*2) = qlw;
            *(uint2*)(sm + OF_KDH + t*272 + d4*2) = khw;
            *(uint2*)(sm + OF_KDL + t*272 + d4*2) = klw;
        }
#pragma unroll
        for (int mt = 0; mt < 2; ++mt)
#pragma unroll
            for (int f = 0; f < 4; ++f)
#pragma unroll
                for (int hh = 0; hh < 2; ++hh) {
                    int d  = m0u + mt*16 + hh*8 + g8;
                    int vc = vcol0 + f*8 + q2;
                    float v0 = S_reg[mt][f][hh*2+0];
                    float v1 = S_reg[mt][f][hh*2+1];
                    __nv_bfloat16 s0 = __float2bfloat16(v0), s1 = __float2bfloat16(v1);
                    *(uint32_t*)(sm + OF_SBH + d*272 + vc*2) = packbf2(v0, v1);
                    *(uint32_t*)(sm + OF_SBL + d*272 + vc*2) =
                        packbf2(v0 - __bfloat162float(s0), v1 - __bfloat162float(s1));
                }
        __syncthreads();

        // ---- P3: A = qe @ kd^T ; skip all-zero (fully masked) warp blocks ----
        {
            float acc[2][4];
#pragma unroll
            for (int f = 0; f < 2; ++f)
#pragma unroll
                for (int j = 0; j < 4; ++j) acc[f][j] = 0.f;
            if (n4 <= wm4) {
#pragma unroll
                for (int ks = 0; ks < 8; ++ks) {
                    int kb = ks * 32;
                    uint32_t aH[4], aL[4];
                    ldsm4(aH, sb + OF_QEH + (m0w + aRow)*272 + kb + aSel);
                    ldsm4(aL, sb + OF_QEL + (m0w + aRow)*272 + kb + aSel);
                    uint32_t bh[4], bl[4];
                    ldsm4(bh, sb + OF_KDH + (sA0 + bRowL)*272 + kb + bKof);
                    ldsm4(bl, sb + OF_KDL + (sA0 + bRowL)*272 + kb + bKof);
                    mma16816(acc[0], aH, bh[0], bh[1]);
                    mma16816(acc[1], aH, bh[2], bh[3]);
                    mma16816(acc[0], aH, bl[0], bl[1]);
                    mma16816(acc[1], aH, bl[2], bl[3]);
                    mma16816(acc[0], aL, bh[0], bh[1]);
                    mma16816(acc[1], aL, bh[2], bh[3]);
                }
            }
            __syncthreads();   // sg reads done; overlay A into sg region
#pragma unroll
            for (int f = 0; f < 2; ++f) {
                int scol = sA0 + f*8 + q2;
#pragma unroll
                for (int hh = 0; hh < 2; ++hh) {
                    int t = m0w + g8 + hh*8;
                    float v0 = (scol     <= t) ? acc[f][hh*2+0] : 0.f;
                    float v1 = (scol + 1 <= t) ? acc[f][hh*2+1] : 0.f;
                    __nv_bfloat16 a0 = __float2bfloat16(v0), a1 = __float2bfloat16(v1);
                    *(uint32_t*)(sm + OF_AH + t*144 + scol*2) = packbf2(v0, v1);
                    *(uint32_t*)(sm + OF_AL + t*144 + scol*2) =
                        packbf2(v0 - __bfloat162float(a0), v1 - __bfloat162float(a1));
                }
            }
        }
        __syncthreads();

        // ---- P4: o = qe@Sb + A@v -> gmem ; U = kd^T@v into S_reg ----
        {
            float acc[4][4];
#pragma unroll
            for (int f = 0; f < 4; ++f)
#pragma unroll
                for (int j = 0; j < 4; ++j) acc[f][j] = 0.f;
            // qe @ Sb  (k = d = 128)
#pragma unroll
            for (int ks = 0; ks < 8; ++ks) {
                int kb = ks * 32;
                uint32_t aH[4], aL[4];
                ldsm4(aH, sb + OF_QEH + (m0w + aRow)*272 + kb + aSel);
                ldsm4(aL, sb + OF_QEL + (m0w + aRow)*272 + kb + aSel);
                uint32_t b0h[4], b1h[4], b0l[4], b1l[4];
                uint32_t sr = (ks*16 + vRow)*272;
                ldsm4t(b0h, sb + OF_SBH + sr + vcol0*2 + vSel);
                ldsm4t(b1h, sb + OF_SBH + sr + (vcol0 + 16)*2 + vSel);
                ldsm4t(b0l, sb + OF_SBL + sr + vcol0*2 + vSel);
                ldsm4t(b1l, sb + OF_SBL + sr + (vcol0 + 16)*2 + vSel);
                mma16816(acc[0], aH, b0h[0], b0h[1]);
                mma16816(acc[1], aH, b0h[2], b0h[3]);
                mma16816(acc[2], aH, b1h[0], b1h[1]);
                mma16816(acc[3], aH, b1h[2], b1h[3]);
                mma16816(acc[0], aH, b0l[0], b0l[1]);
                mma16816(acc[1], aH, b0l[2], b0l[3]);
                mma16816(acc[2], aH, b1l[0], b1l[1]);
                mma16816(acc[3], aH, b1l[2], b1l[3]);
                mma16816(acc[0], aL, b0h[0], b0h[1]);
                mma16816(acc[1], aL, b0h[2], b0h[3]);
                mma16816(acc[2], aL, b1h[0], b1h[1]);
                mma16816(acc[3], aL, b1h[2], b1h[3]);
            }
            // A@v (k limited to causal triangle: ks <= wm4) and kd^T@v (full k)
#pragma unroll 4
            for (int ks = 0; ks < 4; ++ks) {
                int kb = ks * 32;
                uint32_t b0h[4], b1h[4], b0l[4], b1l[4];
                uint32_t vr = (ks*16 + vRow)*272;
                ldsm4t(b0h, sb + OF_VH + vr + vcol0*2 + vSel);
                ldsm4t(b1h, sb + OF_VH + vr + (vcol0 + 16)*2 + vSel);
                ldsm4t(b0l, sb + OF_VL + vr + vcol0*2 + vSel);
                ldsm4t(b1l, sb + OF_VL + vr + (vcol0 + 16)*2 + vSel);
                if (ks <= wm4) {
                    uint32_t aH[4], aL[4];
                    ldsm4(aH, sb + OF_AH + (m0w + aRow)*144 + kb + aSel);
                    ldsm4(aL, sb + OF_AL + (m0w + aRow)*144 + kb + aSel);
                    mma16816(acc[0], aH, b0h[0], b0h[1]);
                    mma16816(acc[1], aH, b0h[2], b0h[3]);
                    mma16816(acc[2], aH, b1h[0], b1h[1]);
                    mma16816(acc[3], aH, b1h[2], b1h[3]);
                    mma16816(acc[0], aH, b0l[0], b0l[1]);
                    mma16816(acc[1], aH, b0l[2], b0l[3]);
                    mma16816(acc[2], aH, b1l[0], b1l[1]);
                    mma16816(acc[3], aH, b1l[2], b1l[3]);
                    mma16816(acc[0], aL, b0h[0], b0h[1]);
                    mma16816(acc[1], aL, b0h[2], b0h[3]);
                    mma16816(acc[2], aL, b1h[0], b1h[1]);
                    mma16816(acc[3], aL, b1h[2], b1h[3]);
                }
                // kd^T @ v -> S_reg
                uint32_t tr = (ks*16 + tRowT)*272;
#pragma unroll
                for (int mt = 0; mt < 2; ++mt) {
                    uint32_t dby = (m0u + mt*16)*2 + tSelT;
                    uint32_t aTh[4], aTl[4];
                    ldsm4t(aTh, sb + OF_KDH + tr + dby);
                    ldsm4t(aTl, sb + OF_KDL + tr + dby);
                    mma16816(S_reg[mt][0], aTh, b0h[0], b0h[1]);
                    mma16816(S_reg[mt][1], aTh, b0h[2], b0h[3]);
                    mma16816(S_reg[mt][2], aTh, b1h[0], b1h[1]);
                    mma16816(S_reg[mt][3], aTh, b1h[2], b1h[3]);
                    mma16816(S_reg[mt][0], aTh, b0l[0], b0l[1]);
                    mma16816(S_reg[mt][1], aTh, b0l[2], b0l[3]);
                    mma16816(S_reg[mt][2], aTh, b1l[0], b1l[1]);
                    mma16816(S_reg[mt][3], aTh, b1l[2], b1l[3]);
                    mma16816(S_reg[mt][0], aTl, b0h[0], b0h[1]);
                    mma16816(S_reg[mt][1], aTl, b0h[2], b0h[3]);
                    mma16816(S_reg[mt][2], aTl, b1h[0], b1h[1]);
                    mma16816(S_reg[mt][3], aTl, b1h[2], b1h[3]);
                }
            }
            // write o
#pragma unroll
            for (int f = 0; f < 4; ++f) {
                int col = vcol0 + f*8 + q2;
#pragma unroll
                for (int hh = 0; hh < 2; ++hh) {
                    int t = m0w + g8 + hh*8;
                    int tg = dir ? (NN-1 - (c*64 + t)) : (c*64 + t);
                    float2 vv; vv.x = acc[f][hh*2+0]; vv.y = acc[f][hh*2+1];
                    *(float2*)&outp[(size_t)(bh*NN + tg)*256 + vs*128 + col] = vv;
                }
            }
            // S *= exp(btot)
#pragma unroll
            for (int mt = 0; mt < 2; ++mt)
#pragma unroll
                for (int hh = 0; hh < 2; ++hh) {
                    float e = ebt[m0u + mt*16 + hh*8 + g8];
#pragma unroll
                    for (int f = 0; f < 4; ++f) {
                        S_reg[mt][f][hh*2+0] *= e;
                        S_reg[mt][f][hh*2+1] *= e;
                    }
                }
        }
        __syncthreads();
    }
}

// ---------------------------------------------------------------------------
// 6) combine — warp-per-token (8 tokens/block), shuffle-only reduction
// ---------------------------------------------------------------------------
__global__ void __launch_bounds__(256) combine_k(const float* __restrict__ gnw,
                                                 const float* __restrict__ lnw)
{
    int tok  = blockIdx.x*8 + (threadIdx.x >> 5);   // 0 .. BB*NH*NN-1
    int lane = threadIdx.x & 31;
    int bh = tok / NN, t = tok % NN;
    int b  = bh >> 2,  h = bh & 3;
    int v0 = lane * 8;

    size_t base = (size_t)tok*256 + v0;
    float4 of0 = *(const float4*)&g_of[base];
    float4 of1 = *(const float4*)&g_of[base+4];
    float4 ob0 = *(const float4*)&g_ob[base];
    float4 ob1 = *(const float4*)&g_ob[base+4];

    float sf = of0.x*of0.x + of0.y*of0.y + of0.z*of0.z + of0.w*of0.w
             + of1.x*of1.x + of1.y*of1.y + of1.z*of1.z + of1.w*of1.w;
    float sb = ob0.x*ob0.x + ob0.y*ob0.y + ob0.z*ob0.z + ob0.w*ob0.w
             + ob1.x*ob1.x + ob1.y*ob1.y + ob1.z*ob1.z + ob1.w*ob1.w;
#pragma unroll
    for (int o = 16; o > 0; o >>= 1) {
        sf += __shfl_xor_sync(0xffffffffu, sf, o);
        sb += __shfl_xor_sync(0xffffffffu, sb, o);
    }
    float inf_ = rsqrtf(sf*(1.f/256.f) + 1e-5f);
    float inb_ = rsqrtf(sb*(1.f/256.f) + 1e-5f);

    float4 gn0 = *(const float4*)&gnw[v0], gn1 = *(const float4*)&gnw[v0+4];
    float4 ln0 = *(const float4*)&lnw[v0], ln1 = *(const float4*)&lnw[v0+4];
    size_t gi = (size_t)(b*NN + t)*1024 + h*256 + v0;
    float4 gg0 = *(const float4*)&g_g[gi];
    float4 gg1 = *(const float4*)&g_g[gi+4];

    float ov[8];
    ov[0] = (of0.x*inf_*gn0.x + ob0.x*inb_*ln0.x) * gg0.x;
    ov[1] = (of0.y*inf_*gn0.y + ob0.y*inb_*ln0.y) * gg0.y;
    ov[2] = (of0.z*inf_*gn0.z + ob0.z*inb_*ln0.z) * gg0.z;
    ov[3] = (of0.w*inf_*gn0.w + ob0.w*inb_*ln0.w) * gg0.w;
    ov[4] = (of1.x*inf_*gn1.x + ob1.x*inb_*ln1.x) * gg1.x;
    ov[5] = (of1.y*inf_*gn1.y + ob1.y*inb_*ln1.y) * gg1.y;
    ov[6] = (of1.z*inf_*gn1.z + ob1.z*inb_*ln1.z) * gg1.z;
    ov[7] = (of1.w*inf_*gn1.w + ob1.w*inb_*ln1.w) * gg1.w;

    __half hh[8], hl[8];
#pragma unroll
    for (int i = 0; i < 8; ++i) {
        hh[i] = __float2half(ov[i]);
        hl[i] = __float2half(ov[i] - __half2float(hh[i]));
    }
    *(uint4*)&g_oc_h[gi] = *(uint4*)hh;
    *(uint4*)&g_oc_l[gi] = *(uint4*)hl;
}

// ---------------------------------------------------------------------------
// launcher
// ---------------------------------------------------------------------------
extern "C" void kernel_launch(void* const* d_in, const int* in_sizes, int n_in,
                              void* d_out, int out_size)
{
    const float* x     = (const float*)d_in[0];
    const float* convw = (const float*)d_in[1];
    const float* qkvw  = (const float*)d_in[2];
    const float* gkw1  = (const float*)d_in[3];
    const float* gkw2  = (const float*)d_in[4];
    const float* gkb2  = (const float*)d_in[5];
    const float* gw    = (const float*)d_in[6];
    const float* gb    = (const float*)d_in[7];
    const float* gnw   = (const float*)d_in[8];
    const float* lnw   = (const float*)d_in[9];
    const float* ow    = (const float*)d_in[10];
    float* out = (float*)d_out;

    cudaFuncSetAttribute(gla_k, cudaFuncAttributeMaxDynamicSharedMemorySize, GLA_SMEM_BYTES);
    cudaFuncSetAttribute(gemm128_k<0>, cudaFuncAttributeMaxDynamicSharedMemorySize, GEMM_SMEM);
    cudaFuncSetAttribute(gemm128_k<2>, cudaFuncAttributeMaxDynamicSharedMemorySize, GEMM_SMEM);

    float *p_qkv, *p_g;
    __half *p_xs_h, *p_xs_l, *p_oc_h, *p_oc_l;
    __half *p_wqg_h, *p_wo_h;
    cudaGetSymbolAddress((void**)&p_qkv,  g_qkv);
    cudaGetSymbolAddress((void**)&p_g,    g_g);
    cudaGetSymbolAddress((void**)&p_xs_h, g_xs_h);
    cudaGetSymbolAddress((void**)&p_xs_l, g_xs_l);
    cudaGetSymbolAddress((void**)&p_oc_h, g_oc_h);
    cudaGetSymbolAddress((void**)&p_oc_l, g_oc_l);
    cudaGetSymbolAddress((void**)&p_wqg_h, g_wqg_h);
    cudaGetSymbolAddress((void**)&p_wo_h, g_wo_h);

    cvt_h_k<<<(2048*512 + 255)/256, 256>>>(qkvw, p_wqg_h, 2048*512);
    cvt_h_k<<<(1024*512 + 255)/256, 256>>>(gw,   p_wqg_h + 2048*512, 1024*512);
    cvt_h_k<<<(512*1024 + 255)/256, 256>>>(ow,   p_wo_h, 512*1024);

    conv_silu_k<<<MROWS, 512>>>(x, convw);

    // fused qkv + gate GEMM (N = 3072)
    gemm128_k<2><<<dim3(3072/128, MROWS/128), 256, GEMM_SMEM>>>(
        p_xs_h, p_xs_l, p_wqg_h, gb, p_qkv, p_g, 0, 512);

    gk1_k<<<MROWS/64, 256>>>(gkw1);
    gk2_k<<<dim3(4, MROWS/64), 256>>>(gkw2, gkb2);
    gla_k<<<dim3(2, BB*NH, 2), 512, GLA_SMEM_BYTES>>>();
    combine_k<<<BB*NH*NN/8, 256>>>(gnw, lnw);

    gemm128_k<0><<<dim3(512/128, MROWS/128), 256, GEMM_SMEM>>>(
        p_oc_h, p_oc_l, p_wo_h, nullptr, out, nullptr, 512, 1024);
}